// round 8
// baseline (speedup 1.0000x reference)
#include <cuda_runtime.h>
#include <cuda_bf16.h>
#include <cstdint>

#define TOKENS 8192
#define DM 1024
#define DH 4096
#define NE 8
#define NSLOTS (TOKENS * 2)

// GEMM tiling: CTA 128x128x32, 8 warps (2m x 4n), warp tile 64x32
// SMEM: XOR-swizzled 64B rows, no padding. Stage = 4 tensors * 128 rows * 64B = 32KB.
#define BM 128
#define BN 128
#define BK 32
#define NSTG 3
#define OFF_AH 0
#define OFF_AL 8192
#define OFF_BH 16384
#define OFF_BL 24576
#define STAGE_BYTES 32768
#define SMEM_TOTAL (NSTG * STAGE_BYTES)   // 98304 -> 2 CTAs/SM

// ---------------- scratch globals ----------------
__device__ __nv_bfloat16 g_xl_hi[(size_t)TOKENS * DM];
__device__ __nv_bfloat16 g_xl_lo[(size_t)TOKENS * DM];
__device__ __nv_bfloat16 g_w1t_hi[(size_t)NE * DH * DM];   // [E][N=DH][K=DM]
__device__ __nv_bfloat16 g_w1t_lo[(size_t)NE * DH * DM];
__device__ __nv_bfloat16 g_w2t_hi[(size_t)NE * DM * DH];   // [E][N=DM][K=DH]
__device__ __nv_bfloat16 g_w2t_lo[(size_t)NE * DM * DH];
__device__ __nv_bfloat16 g_h_hi[(size_t)NSLOTS * DH];
__device__ __nv_bfloat16 g_h_lo[(size_t)NSLOTS * DH];
__device__ float g_o[(size_t)NSLOTS * DM];
__device__ int g_top2[TOKENS];
__device__ int2 g_slots[TOKENS];
__device__ int g_counts[NE];
__device__ int g_offsets[NE];
__device__ int g_cursor[NE];
__device__ int g_tokens[NSLOTS];
__device__ int g_done;

// ---------------- PTX helpers ----------------
__device__ __forceinline__ uint32_t smem_u32(const void* p) {
    uint32_t a;
    asm("{ .reg .u64 t; cvta.to.shared.u64 t, %1; cvt.u32.u64 %0, t; }" : "=r"(a) : "l"(p));
    return a;
}
__device__ __forceinline__ void cp_async16(uint32_t dst, const void* src) {
    asm volatile("cp.async.cg.shared.global [%0], [%1], 16;" :: "r"(dst), "l"(src));
}
__device__ __forceinline__ void cp_commit() { asm volatile("cp.async.commit_group;" ::: "memory"); }
template <int N>
__device__ __forceinline__ void cp_wait() { asm volatile("cp.async.wait_group %0;" :: "n"(N) : "memory"); }

__device__ __forceinline__ void ldsm4(uint32_t* r, uint32_t addr) {
    asm volatile("ldmatrix.sync.aligned.m8n8.x4.shared.b16 {%0,%1,%2,%3}, [%4];"
                 : "=r"(r[0]), "=r"(r[1]), "=r"(r[2]), "=r"(r[3]) : "r"(addr));
}
__device__ __forceinline__ void mma_bf16(float* c, const uint32_t* a, const uint32_t* b) {
    asm volatile(
        "mma.sync.aligned.m16n8k16.row.col.f32.bf16.bf16.f32 "
        "{%0,%1,%2,%3}, {%4,%5,%6,%7}, {%8,%9}, {%0,%1,%2,%3};"
        : "+f"(c[0]), "+f"(c[1]), "+f"(c[2]), "+f"(c[3])
        : "r"(a[0]), "r"(a[1]), "r"(a[2]), "r"(a[3]), "r"(b[0]), "r"(b[1]));
}

// swizzled offset within a 128x64B tile: row r (0..127), 16B chunk c (0..3)
__device__ __forceinline__ uint32_t swz(int r, int c) {
    return (uint32_t)r * 64u + (uint32_t)((c ^ ((r >> 1) & 3)) << 4);
}

// ---------------- kernel 1: fused prep ----------------
// z == 0:        cvt xl -> bf16 hi/lo (grid.x*y covers TOKENS*DM/1024) + reset counters
// z in [1..8]:   W1 expert z-1 transpose-convert
// z in [9..16]:  W2 expert z-9 transpose-convert
__global__ void k_prep(const float* __restrict__ xl,
                       const float* __restrict__ W1, const float* __restrict__ W2) {
    const int z = blockIdx.z;
    if (z == 0) {
        // only a slice of blocks do x conversion; grid sized so x*y covers it
        const size_t nblk = (size_t)gridDim.x * gridDim.y;
        const size_t bid = (size_t)blockIdx.y * gridDim.x + blockIdx.x;
        if (bid == 0 && threadIdx.x < NE + 1) {
            if (threadIdx.x < NE) g_counts[threadIdx.x] = 0;
            else g_done = 0;
        }
        const int tid = threadIdx.x + (threadIdx.y << 5);
        const size_t total4 = (size_t)TOKENS * DM / 4;          // float4 count
        for (size_t i = bid * 256 + tid; i < total4; i += nblk * 256) {
            float4 v = *reinterpret_cast<const float4*>(xl + i * 4);
            __nv_bfloat162 h01 = __floats2bfloat162_rn(v.x, v.y);
            __nv_bfloat162 h23 = __floats2bfloat162_rn(v.z, v.w);
            __nv_bfloat162 l01 = __floats2bfloat162_rn(v.x - __bfloat162float(h01.x),
                                                       v.y - __bfloat162float(h01.y));
            __nv_bfloat162 l23 = __floats2bfloat162_rn(v.z - __bfloat162float(h23.x),
                                                       v.w - __bfloat162float(h23.y));
            uint2 hv = make_uint2(*(uint32_t*)&h01, *(uint32_t*)&h23);
            uint2 lv = make_uint2(*(uint32_t*)&l01, *(uint32_t*)&l23);
            *reinterpret_cast<uint2*>(g_xl_hi + i * 4) = hv;
            *reinterpret_cast<uint2*>(g_xl_lo + i * 4) = lv;
        }
        return;
    }
    // weight transpose-convert (32x32 tiles)
    __shared__ float t[32][33];
    const int which = (z - 1) >> 3, e = (z - 1) & 7;
    int n0, k0, K, N;
    const float* W;
    __nv_bfloat16 *Ohi, *Olo;
    if (!which) { K = DM; N = DH; n0 = blockIdx.x * 32; k0 = blockIdx.y * 32;
                  W = W1; Ohi = g_w1t_hi; Olo = g_w1t_lo; }
    else        { K = DH; N = DM; k0 = blockIdx.x * 32; n0 = blockIdx.y * 32;
                  W = W2; Ohi = g_w2t_hi; Olo = g_w2t_lo; }
    if (n0 >= N || k0 >= K) return;
    const float* Wp = W + (size_t)e * K * N;
    const int tx = threadIdx.x, ty = threadIdx.y;
#pragma unroll
    for (int j = 0; j < 4; j++)
        t[ty + j * 8][tx] = Wp[(size_t)(k0 + ty + j * 8) * N + n0 + tx];
    __syncthreads();
#pragma unroll
    for (int j = 0; j < 4; j++) {
        int n = n0 + ty + j * 8;
        float v = t[tx][ty + j * 8];
        __nv_bfloat16 h = __float2bfloat16(v);
        size_t o = ((size_t)e * N + n) * K + k0 + tx;
        Ohi[o] = h;
        Olo[o] = __float2bfloat16(v - __bfloat162float(h));
    }
}

// ---------------- kernel 2: gating + last-block scan & parallel scatter ----------------
__global__ void k_gating_route(const float* __restrict__ x0, const float* __restrict__ Wg) {
    const int warp = threadIdx.x >> 5, lane = threadIdx.x & 31;
    const int t = blockIdx.x * (blockDim.x >> 5) + warp;
    {
        double acc[NE];
#pragma unroll
        for (int e = 0; e < NE; e++) acc[e] = 0.0;
        const float* x = x0 + (size_t)t * DM;
        for (int k = lane; k < DM; k += 32) {
            float xv = x[k];
            const float4 w0 = *reinterpret_cast<const float4*>(Wg + (size_t)k * NE);
            const float4 w1 = *reinterpret_cast<const float4*>(Wg + (size_t)k * NE + 4);
            acc[0] += (double)xv * w0.x; acc[1] += (double)xv * w0.y;
            acc[2] += (double)xv * w0.z; acc[3] += (double)xv * w0.w;
            acc[4] += (double)xv * w1.x; acc[5] += (double)xv * w1.y;
            acc[6] += (double)xv * w1.z; acc[7] += (double)xv * w1.w;
        }
#pragma unroll
        for (int off = 16; off > 0; off >>= 1)
#pragma unroll
            for (int e = 0; e < NE; e++) acc[e] += __shfl_xor_sync(0xffffffffu, acc[e], off);
        if (lane == 0) {
            int i1 = 0; double v1 = acc[0];
#pragma unroll
            for (int e = 1; e < NE; e++) if (acc[e] > v1) { v1 = acc[e]; i1 = e; }
            int i2 = -1; double v2 = -1.0e300;
#pragma unroll
            for (int e = 0; e < NE; e++) if (e != i1 && acc[e] > v2) { v2 = acc[e]; i2 = e; }
            g_top2[t] = i1 | (i2 << 8);
            atomicAdd(&g_counts[i1], 1);
            atomicAdd(&g_counts[i2], 1);
        }
    }
    __shared__ int isLast;
    __syncthreads();
    if (threadIdx.x == 0) {
        __threadfence();
        isLast = (atomicAdd(&g_done, 1) == (int)gridDim.x - 1) ? 1 : 0;
    }
    __syncthreads();
    if (!isLast) return;
    __threadfence();
    if (threadIdx.x == 0) {
        int s = 0;
        for (int e = 0; e < NE; e++) { g_offsets[e] = s; g_cursor[e] = s; s += g_counts[e]; }
    }
    __syncthreads();
    for (int tk = threadIdx.x; tk < TOKENS; tk += blockDim.x) {
        int p = g_top2[tk];
        int s1 = atomicAdd(&g_cursor[p & 0xff], 1);
        int s2 = atomicAdd(&g_cursor[(p >> 8) & 0xff], 1);
        g_tokens[s1] = tk;
        g_tokens[s2] = tk;
        g_slots[tk] = make_int2(s1, s2);
    }
}

// ---------------- HMMA GEMM inner loop (unchanged from R6/R7 winner) ----------------
__device__ __forceinline__ void compute_stage(uint32_t st, float acc[4][4][4],
                                              uint32_t aoff, uint32_t boff) {
#pragma unroll
    for (int k16 = 0; k16 < 2; k16++) {
        const uint32_t ab = st + OFF_AH + (aoff ^ (k16 << 5));
        const uint32_t bb = st + OFF_BH + (boff ^ (k16 << 5));
        uint32_t af[4][4], bh[2][4], bl[2][4];
#pragma unroll
        for (int mt = 0; mt < 4; mt++) ldsm4(af[mt], ab + mt * 1024);
#pragma unroll
        for (int p = 0; p < 2; p++)   ldsm4(bh[p], bb + p * 1024);
#pragma unroll
        for (int p = 0; p < 2; p++)   ldsm4(bl[p], bb + (OFF_BL - OFF_BH) + p * 1024);
        // pass 1: Ahi * Bhi
#pragma unroll
        for (int mt = 0; mt < 4; mt++)
#pragma unroll
            for (int nt = 0; nt < 4; nt++)
                mma_bf16(acc[mt][nt], af[mt], &bh[nt >> 1][(nt & 1) * 2]);
        // pass 2: Ahi * Blo
#pragma unroll
        for (int mt = 0; mt < 4; mt++)
#pragma unroll
            for (int nt = 0; nt < 4; nt++)
                mma_bf16(acc[mt][nt], af[mt], &bl[nt >> 1][(nt & 1) * 2]);
        // pass 3: Alo * Bhi (reload A frags from lo tile)
#pragma unroll
        for (int mt = 0; mt < 4; mt++) ldsm4(af[mt], ab + (OFF_AL - OFF_AH) + mt * 1024);
#pragma unroll
        for (int mt = 0; mt < 4; mt++)
#pragma unroll
            for (int nt = 0; nt < 4; nt++)
                mma_bf16(acc[mt][nt], af[mt], &bh[nt >> 1][(nt & 1) * 2]);
    }
}

template <int KT, int NTOT, bool IS_G1>
__global__ __launch_bounds__(256, 2) void k_hmma(const float* __restrict__ bias) {
    const int e = blockIdx.z;
    const int cnt = g_counts[e];
    const int m0 = blockIdx.y * BM;
    if (m0 >= cnt) return;
    const int off = g_offsets[e];
    const int n0 = blockIdx.x * BN;
    const int tid = threadIdx.x;

    extern __shared__ char smem[];
    __shared__ int s_rows[BM];
    const uint32_t sb = smem_u32(smem);

    if (tid < BM) {
        int mm = m0 + tid;
        int mc = mm < cnt ? mm : cnt - 1;
        s_rows[tid] = IS_G1 ? g_tokens[off + mc] : (off + mc);
    }
    __syncthreads();

    const __nv_bfloat16* Ahi = IS_G1 ? g_xl_hi : g_h_hi;
    const __nv_bfloat16* Alo = IS_G1 ? g_xl_lo : g_h_lo;
    const __nv_bfloat16* Bhi = (IS_G1 ? g_w1t_hi : g_w2t_hi) + ((size_t)e * NTOT + n0) * KT;
    const __nv_bfloat16* Blo = (IS_G1 ? g_w1t_lo : g_w2t_lo) + ((size_t)e * NTOT + n0) * KT;

    const int rF = tid >> 2, cF = tid & 3;
    const uint32_t d0 = swz(rF, cF);
    const uint32_t d1 = d0 + 64 * 64;
    const __nv_bfloat16* ah0 = Ahi + (size_t)s_rows[rF] * KT + cF * 8;
    const __nv_bfloat16* al0 = Alo + (size_t)s_rows[rF] * KT + cF * 8;
    const __nv_bfloat16* ah1 = Ahi + (size_t)s_rows[rF + 64] * KT + cF * 8;
    const __nv_bfloat16* al1 = Alo + (size_t)s_rows[rF + 64] * KT + cF * 8;
    const __nv_bfloat16* bh0 = Bhi + (size_t)rF * KT + cF * 8;
    const __nv_bfloat16* bl0 = Blo + (size_t)rF * KT + cF * 8;
    const __nv_bfloat16* bh1 = Bhi + (size_t)(rF + 64) * KT + cF * 8;
    const __nv_bfloat16* bl1 = Blo + (size_t)(rF + 64) * KT + cF * 8;

#define FILL(sidx, k0_) do {                                        \
        uint32_t _s = sb + (sidx) * STAGE_BYTES;                    \
        cp_async16(_s + OFF_AH + d0, ah0 + (k0_));                  \
        cp_async16(_s + OFF_AH + d1, ah1 + (k0_));                  \
        cp_async16(_s + OFF_AL + d0, al0 + (k0_));                  \
        cp_async16(_s + OFF_AL + d1, al1 + (k0_));                  \
        cp_async16(_s + OFF_BH + d0, bh0 + (k0_));                  \
        cp_async16(_s + OFF_BH + d1, bh1 + (k0_));                  \
        cp_async16(_s + OFF_BL + d0, bl0 + (k0_));                  \
        cp_async16(_s + OFF_BL + d1, bl1 + (k0_));                  \
    } while (0)

    const int lane = tid & 31, wid = tid >> 5;
    const int warp_m = wid >> 2, warp_n = wid & 3;
    const int rowA = warp_m * 64 + (lane & 15);
    const int rowB = warp_n * 32 + ((lane >> 4) << 3) + (lane & 7);
    const uint32_t aoff = swz(rowA, lane >> 4);
    const uint32_t boff = swz(rowB, (lane >> 3) & 1);

    float acc[4][4][4];
#pragma unroll
    for (int i = 0; i < 4; i++)
#pragma unroll
        for (int j = 0; j < 4; j++)
#pragma unroll
            for (int q = 0; q < 4; q++) acc[i][j][q] = 0.f;

    constexpr int NKC = KT / BK;
    FILL(0, 0);  cp_commit();
    FILL(1, BK); cp_commit();

    for (int kc = 0; kc < NKC; kc++) {
        cp_wait<1>();
        __syncthreads();
        if (kc + 2 < NKC) { FILL((kc + 2) % NSTG, (kc + 2) * BK); }
        cp_commit();
        compute_stage(sb + (kc % NSTG) * STAGE_BYTES, acc, aoff, boff);
    }
#undef FILL

    // ---- epilogue ----
    const int g = lane >> 2, c2 = (lane & 3) * 2;
    const float* bp = bias + (size_t)e * NTOT;
#pragma unroll
    for (int mt = 0; mt < 4; mt++) {
#pragma unroll
        for (int nt = 0; nt < 4; nt++) {
            const int n = n0 + warp_n * 32 + nt * 8 + c2;
            const float bv0 = __ldg(bp + n), bv1 = __ldg(bp + n + 1);
#pragma unroll
            for (int h = 0; h < 2; h++) {
                const int m = m0 + warp_m * 64 + mt * 16 + g + h * 8;
                if (m >= cnt) continue;
                float v0 = acc[mt][nt][h * 2 + 0] + bv0;
                float v1 = acc[mt][nt][h * 2 + 1] + bv1;
                if (IS_G1) {
                    v0 = fmaxf(v0, 0.f); v1 = fmaxf(v1, 0.f);
                    __nv_bfloat162 h2 = __floats2bfloat162_rn(v0, v1);
                    __nv_bfloat162 l2 = __floats2bfloat162_rn(
                        v0 - __bfloat162float(h2.x), v1 - __bfloat162float(h2.y));
                    const size_t o = (size_t)(off + m) * DH + n;
                    *reinterpret_cast<uint32_t*>(g_h_hi + o) = *reinterpret_cast<uint32_t*>(&h2);
                    *reinterpret_cast<uint32_t*>(g_h_lo + o) = *reinterpret_cast<uint32_t*>(&l2);
                } else {
                    float2 v = make_float2(v0, v1);
                    *reinterpret_cast<float2*>(g_o + (size_t)(off + m) * DM + n) = v;
                }
            }
        }
    }
}

// ---------------- kernel 5: combine out[t] = g_o[s1] + g_o[s2] ----------------
__global__ void k_combine(float* __restrict__ out) {
    const int i = blockIdx.x * blockDim.x + threadIdx.x;   // float4 index
    const int t = i >> 8, cc = i & 255;
    const int2 s = g_slots[t];
    const float4 a = *reinterpret_cast<const float4*>(g_o + (size_t)s.x * DM + cc * 4);
    const float4 b = *reinterpret_cast<const float4*>(g_o + (size_t)s.y * DM + cc * 4);
    float4 r = make_float4(a.x + b.x, a.y + b.y, a.z + b.z, a.w + b.w);
    *reinterpret_cast<float4*>(out + (size_t)t * DM + cc * 4) = r;
}

// ---------------- launch ----------------
extern "C" void kernel_launch(void* const* d_in, const int* in_sizes, int n_in,
                              void* d_out, int out_size) {
    const float* xl = (const float*)d_in[0];
    const float* x0 = (const float*)d_in[1];
    const float* Wg = (const float*)d_in[2];
    const float* W1 = (const float*)d_in[3];
    const float* b1 = (const float*)d_in[4];
    const float* W2 = (const float*)d_in[5];
    const float* b2 = (const float*)d_in[6];
    float* out = (float*)d_out;

    cudaFuncSetAttribute((const void*)k_hmma<DM, DH, true>,
                         cudaFuncAttributeMaxDynamicSharedMemorySize, SMEM_TOTAL);
    cudaFuncSetAttribute((const void*)k_hmma<DH, DM, false>,
                         cudaFuncAttributeMaxDynamicSharedMemorySize, SMEM_TOTAL);

    // 1: prep (x convert + both weight transposes), z=0 x-cvt, z=1..16 weights
    k_prep<<<dim3(128, 32, 17), dim3(32, 8)>>>(xl, W1, W2);
    // 2: gating + scan + scatter
    k_gating_route<<<TOKENS / 8, 256>>>(x0, Wg);
    // 3: GEMM1
    k_hmma<DM, DH, true><<<dim3(DH / BN, TOKENS / BM, NE), 256, SMEM_TOTAL>>>(b1);
    // 4: GEMM2  (profiled slot)
    k_hmma<DH, DM, false><<<dim3(DM / BN, TOKENS / BM, NE), 256, SMEM_TOTAL>>>(b2);
    // 5: combine
    k_combine<<<(TOKENS * DM / 4) / 256, 256>>>(out);
}

// round 9
// speedup vs baseline: 1.0074x; 1.0074x over previous
#include <cuda_runtime.h>
#include <cuda_bf16.h>
#include <cstdint>

#define TOKENS 8192
#define DM 1024
#define DH 4096
#define NE 8
#define NSLOTS (TOKENS * 2)

// GEMM tiling: CTA 128x128x32, 8 warps (2m x 4n), warp tile 64x32
// SMEM: XOR-swizzled 64B rows. Stage = 4 tensors * 128 rows * 64B = 32KB; 3 stages -> 2 CTA/SM.
#define BM 128
#define BN 128
#define BK 32
#define NSTG 3
#define OFF_AH 0
#define OFF_AL 8192
#define OFF_BH 16384
#define OFF_BL 24576
#define STAGE_BYTES 32768
#define SMEM_TOTAL (NSTG * STAGE_BYTES)   // 98304

// ---------------- scratch globals ----------------
__device__ __nv_bfloat16 g_xl_hi[(size_t)TOKENS * DM];
__device__ __nv_bfloat16 g_xl_lo[(size_t)TOKENS * DM];
__device__ __nv_bfloat16 g_w1t_hi[(size_t)NE * DH * DM];   // [E][N=DH][K=DM]
__device__ __nv_bfloat16 g_w1t_lo[(size_t)NE * DH * DM];
__device__ __nv_bfloat16 g_w2t_hi[(size_t)NE * DM * DH];   // [E][N=DM][K=DH]
__device__ __nv_bfloat16 g_w2t_lo[(size_t)NE * DM * DH];
__device__ __nv_bfloat16 g_h_hi[(size_t)NSLOTS * DH];
__device__ __nv_bfloat16 g_h_lo[(size_t)NSLOTS * DH];
__device__ int g_top2[TOKENS];
__device__ int g_counts[NE];
__device__ int g_offsets[NE];
__device__ int g_cursor[NE];
__device__ int g_tokens[NSLOTS];

// ---------------- PTX helpers ----------------
__device__ __forceinline__ uint32_t smem_u32(const void* p) {
    uint32_t a;
    asm("{ .reg .u64 t; cvta.to.shared.u64 t, %1; cvt.u32.u64 %0, t; }" : "=r"(a) : "l"(p));
    return a;
}
__device__ __forceinline__ void cp_async16(uint32_t dst, const void* src) {
    asm volatile("cp.async.cg.shared.global [%0], [%1], 16;" :: "r"(dst), "l"(src));
}
__device__ __forceinline__ void cp_commit() { asm volatile("cp.async.commit_group;" ::: "memory"); }
template <int N>
__device__ __forceinline__ void cp_wait() { asm volatile("cp.async.wait_group %0;" :: "n"(N) : "memory"); }

__device__ __forceinline__ void ldsm4(uint32_t* r, uint32_t addr) {
    asm volatile("ldmatrix.sync.aligned.m8n8.x4.shared.b16 {%0,%1,%2,%3}, [%4];"
                 : "=r"(r[0]), "=r"(r[1]), "=r"(r[2]), "=r"(r[3]) : "r"(addr));
}
__device__ __forceinline__ void mma_bf16(float* c, const uint32_t* a, const uint32_t* b) {
    asm volatile(
        "mma.sync.aligned.m16n8k16.row.col.f32.bf16.bf16.f32 "
        "{%0,%1,%2,%3}, {%4,%5,%6,%7}, {%8,%9}, {%0,%1,%2,%3};"
        : "+f"(c[0]), "+f"(c[1]), "+f"(c[2]), "+f"(c[3])
        : "r"(a[0]), "r"(a[1]), "r"(a[2]), "r"(a[3]), "r"(b[0]), "r"(b[1]));
}

// swizzled offset within a 128x64B tile: row r (0..127), 16B chunk c (0..3)
__device__ __forceinline__ uint32_t swz(int r, int c) {
    return (uint32_t)r * 64u + (uint32_t)((c ^ ((r >> 1) & 3)) << 4);
}

// ---------------- kernel: fused prep ----------------
// z == 0:        cvt xl -> bf16 hi/lo (vectorized) + reset counters
// z in [1..8]:   W1 expert z-1 transpose-convert
// z in [9..16]:  W2 expert z-9 transpose-convert
__global__ void k_prep(const float* __restrict__ xl,
                       const float* __restrict__ W1, const float* __restrict__ W2) {
    const int z = blockIdx.z;
    if (z == 0) {
        const size_t nblk = (size_t)gridDim.x * gridDim.y;
        const size_t bid = (size_t)blockIdx.y * gridDim.x + blockIdx.x;
        if (bid == 0 && threadIdx.x < NE && threadIdx.y == 0) g_counts[threadIdx.x] = 0;
        const int tid = threadIdx.x + (threadIdx.y << 5);
        const size_t total4 = (size_t)TOKENS * DM / 4;
        for (size_t i = bid * 256 + tid; i < total4; i += nblk * 256) {
            float4 v = *reinterpret_cast<const float4*>(xl + i * 4);
            __nv_bfloat162 h01 = __floats2bfloat162_rn(v.x, v.y);
            __nv_bfloat162 h23 = __floats2bfloat162_rn(v.z, v.w);
            __nv_bfloat162 l01 = __floats2bfloat162_rn(v.x - __bfloat162float(h01.x),
                                                       v.y - __bfloat162float(h01.y));
            __nv_bfloat162 l23 = __floats2bfloat162_rn(v.z - __bfloat162float(h23.x),
                                                       v.w - __bfloat162float(h23.y));
            uint2 hv = make_uint2(*(uint32_t*)&h01, *(uint32_t*)&h23);
            uint2 lv = make_uint2(*(uint32_t*)&l01, *(uint32_t*)&l23);
            *reinterpret_cast<uint2*>(g_xl_hi + i * 4) = hv;
            *reinterpret_cast<uint2*>(g_xl_lo + i * 4) = lv;
        }
        return;
    }
    __shared__ float t[32][33];
    const int which = (z - 1) >> 3, e = (z - 1) & 7;
    int n0, k0, K, N;
    const float* W;
    __nv_bfloat16 *Ohi, *Olo;
    if (!which) { K = DM; N = DH; n0 = blockIdx.x * 32; k0 = blockIdx.y * 32;
                  W = W1; Ohi = g_w1t_hi; Olo = g_w1t_lo; }
    else        { K = DH; N = DM; k0 = blockIdx.x * 32; n0 = blockIdx.y * 32;
                  W = W2; Ohi = g_w2t_hi; Olo = g_w2t_lo; }
    if (n0 >= N || k0 >= K) return;
    const float* Wp = W + (size_t)e * K * N;
    const int tx = threadIdx.x, ty = threadIdx.y;
#pragma unroll
    for (int j = 0; j < 4; j++)
        t[ty + j * 8][tx] = Wp[(size_t)(k0 + ty + j * 8) * N + n0 + tx];
    __syncthreads();
#pragma unroll
    for (int j = 0; j < 4; j++) {
        int n = n0 + ty + j * 8;
        float v = t[tx][ty + j * 8];
        __nv_bfloat16 h = __float2bfloat16(v);
        size_t o = ((size_t)e * N + n) * K + k0 + tx;
        Ohi[o] = h;
        Olo[o] = __float2bfloat16(v - __bfloat162float(h));
    }
}

// ---------------- gating (top-2 per token, fp64 accumulate) ----------------
__global__ void k_gating(const float* __restrict__ x0, const float* __restrict__ Wg) {
    const int warp = threadIdx.x >> 5, lane = threadIdx.x & 31;
    const int t = blockIdx.x * (blockDim.x >> 5) + warp;
    double acc[NE];
#pragma unroll
    for (int e = 0; e < NE; e++) acc[e] = 0.0;
    const float* x = x0 + (size_t)t * DM;
    for (int k = lane; k < DM; k += 32) {
        float xv = x[k];
        const float4 w0 = *reinterpret_cast<const float4*>(Wg + (size_t)k * NE);
        const float4 w1 = *reinterpret_cast<const float4*>(Wg + (size_t)k * NE + 4);
        acc[0] += (double)xv * w0.x; acc[1] += (double)xv * w0.y;
        acc[2] += (double)xv * w0.z; acc[3] += (double)xv * w0.w;
        acc[4] += (double)xv * w1.x; acc[5] += (double)xv * w1.y;
        acc[6] += (double)xv * w1.z; acc[7] += (double)xv * w1.w;
    }
#pragma unroll
    for (int off = 16; off > 0; off >>= 1)
#pragma unroll
        for (int e = 0; e < NE; e++) acc[e] += __shfl_xor_sync(0xffffffffu, acc[e], off);
    if (lane == 0) {
        int i1 = 0; double v1 = acc[0];
#pragma unroll
        for (int e = 1; e < NE; e++) if (acc[e] > v1) { v1 = acc[e]; i1 = e; }
        int i2 = -1; double v2 = -1.0e300;
#pragma unroll
        for (int e = 0; e < NE; e++) if (e != i1 && acc[e] > v2) { v2 = acc[e]; i2 = e; }
        g_top2[t] = i1 | (i2 << 8);
        atomicAdd(&g_counts[i1], 1);
        atomicAdd(&g_counts[i2], 1);
    }
}

__global__ void k_scan() {
    int s = 0;
    for (int e = 0; e < NE; e++) { g_offsets[e] = s; g_cursor[e] = s; s += g_counts[e]; }
}

__global__ void k_scatter() {
    const int t = blockIdx.x * blockDim.x + threadIdx.x;
    const int p = g_top2[t];
    const int s1 = atomicAdd(&g_cursor[p & 0xff], 1);
    const int s2 = atomicAdd(&g_cursor[(p >> 8) & 0xff], 1);
    g_tokens[s1] = t;
    g_tokens[s2] = t;
}

// ---------------- HMMA GEMM inner loop (R6/R7/R8 winner, unchanged) ----------------
__device__ __forceinline__ void compute_stage(uint32_t st, float acc[4][4][4],
                                              uint32_t aoff, uint32_t boff) {
#pragma unroll
    for (int k16 = 0; k16 < 2; k16++) {
        const uint32_t ab = st + OFF_AH + (aoff ^ (k16 << 5));
        const uint32_t bb = st + OFF_BH + (boff ^ (k16 << 5));
        uint32_t af[4][4], bh[2][4], bl[2][4];
#pragma unroll
        for (int mt = 0; mt < 4; mt++) ldsm4(af[mt], ab + mt * 1024);
#pragma unroll
        for (int p = 0; p < 2; p++)   ldsm4(bh[p], bb + p * 1024);
#pragma unroll
        for (int p = 0; p < 2; p++)   ldsm4(bl[p], bb + (OFF_BL - OFF_BH) + p * 1024);
#pragma unroll
        for (int mt = 0; mt < 4; mt++)
#pragma unroll
            for (int nt = 0; nt < 4; nt++)
                mma_bf16(acc[mt][nt], af[mt], &bh[nt >> 1][(nt & 1) * 2]);
#pragma unroll
        for (int mt = 0; mt < 4; mt++)
#pragma unroll
            for (int nt = 0; nt < 4; nt++)
                mma_bf16(acc[mt][nt], af[mt], &bl[nt >> 1][(nt & 1) * 2]);
#pragma unroll
        for (int mt = 0; mt < 4; mt++) ldsm4(af[mt], ab + (OFF_AL - OFF_AH) + mt * 1024);
#pragma unroll
        for (int mt = 0; mt < 4; mt++)
#pragma unroll
            for (int nt = 0; nt < 4; nt++)
                mma_bf16(acc[mt][nt], af[mt], &bh[nt >> 1][(nt & 1) * 2]);
    }
}

// KT = full K; NSPLIT-way split-K (each CTA does KT/NSPLIT). IS_G1 writes h hi/lo;
// else atomicAdd into out (bias added only by split 0).
template <int KT, int NTOT, bool IS_G1, int NSPLIT>
__global__ __launch_bounds__(256, 2) void k_hmma(const float* __restrict__ bias,
                                                 float* __restrict__ out) {
    const int e = blockIdx.z;
    const int cnt = g_counts[e];
    const int my = blockIdx.y / NSPLIT;
    const int kv = blockIdx.y % NSPLIT;
    const int m0 = my * BM;
    if (m0 >= cnt) return;
    const int off = g_offsets[e];
    const int n0 = blockIdx.x * BN;
    const int tid = threadIdx.x;
    constexpr int KC = KT / NSPLIT;          // per-CTA K
    const int kbase = kv * KC;

    extern __shared__ char smem[];
    __shared__ int s_rows[BM];
    const uint32_t sb = smem_u32(smem);

    if (tid < BM) {
        int mm = m0 + tid;
        int mc = mm < cnt ? mm : cnt - 1;
        s_rows[tid] = IS_G1 ? g_tokens[off + mc] : (off + mc);
    }
    __syncthreads();

    const __nv_bfloat16* Ahi = (IS_G1 ? g_xl_hi : g_h_hi) + kbase;
    const __nv_bfloat16* Alo = (IS_G1 ? g_xl_lo : g_h_lo) + kbase;
    const __nv_bfloat16* Bhi = (IS_G1 ? g_w1t_hi : g_w2t_hi) + ((size_t)e * NTOT + n0) * KT + kbase;
    const __nv_bfloat16* Blo = (IS_G1 ? g_w1t_lo : g_w2t_lo) + ((size_t)e * NTOT + n0) * KT + kbase;

    const int rF = tid >> 2, cF = tid & 3;
    const uint32_t d0 = swz(rF, cF);
    const uint32_t d1 = d0 + 64 * 64;
    const __nv_bfloat16* ah0 = Ahi + (size_t)s_rows[rF] * KT + cF * 8;
    const __nv_bfloat16* al0 = Alo + (size_t)s_rows[rF] * KT + cF * 8;
    const __nv_bfloat16* ah1 = Ahi + (size_t)s_rows[rF + 64] * KT + cF * 8;
    const __nv_bfloat16* al1 = Alo + (size_t)s_rows[rF + 64] * KT + cF * 8;
    const __nv_bfloat16* bh0 = Bhi + (size_t)rF * KT + cF * 8;
    const __nv_bfloat16* bl0 = Blo + (size_t)rF * KT + cF * 8;
    const __nv_bfloat16* bh1 = Bhi + (size_t)(rF + 64) * KT + cF * 8;
    const __nv_bfloat16* bl1 = Blo + (size_t)(rF + 64) * KT + cF * 8;

#define FILL(sidx, k0_) do {                                        \
        uint32_t _s = sb + (sidx) * STAGE_BYTES;                    \
        cp_async16(_s + OFF_AH + d0, ah0 + (k0_));                  \
        cp_async16(_s + OFF_AH + d1, ah1 + (k0_));                  \
        cp_async16(_s + OFF_AL + d0, al0 + (k0_));                  \
        cp_async16(_s + OFF_AL + d1, al1 + (k0_));                  \
        cp_async16(_s + OFF_BH + d0, bh0 + (k0_));                  \
        cp_async16(_s + OFF_BH + d1, bh1 + (k0_));                  \
        cp_async16(_s + OFF_BL + d0, bl0 + (k0_));                  \
        cp_async16(_s + OFF_BL + d1, bl1 + (k0_));                  \
    } while (0)

    const int lane = tid & 31, wid = tid >> 5;
    const int warp_m = wid >> 2, warp_n = wid & 3;
    const int rowA = warp_m * 64 + (lane & 15);
    const int rowB = warp_n * 32 + ((lane >> 4) << 3) + (lane & 7);
    const uint32_t aoff = swz(rowA, lane >> 4);
    const uint32_t boff = swz(rowB, (lane >> 3) & 1);

    float acc[4][4][4];
#pragma unroll
    for (int i = 0; i < 4; i++)
#pragma unroll
        for (int j = 0; j < 4; j++)
#pragma unroll
            for (int q = 0; q < 4; q++) acc[i][j][q] = 0.f;

    constexpr int NKC = KC / BK;
    FILL(0, 0);  cp_commit();
    FILL(1, BK); cp_commit();

    for (int kc = 0; kc < NKC; kc++) {
        cp_wait<1>();
        __syncthreads();
        if (kc + 2 < NKC) { FILL((kc + 2) % NSTG, (kc + 2) * BK); }
        cp_commit();
        compute_stage(sb + (kc % NSTG) * STAGE_BYTES, acc, aoff, boff);
    }
#undef FILL

    // ---- epilogue ----
    const int g = lane >> 2, c2 = (lane & 3) * 2;
    const float* bp = bias + (size_t)e * NTOT;
    const bool addb = (kv == 0);
#pragma unroll
    for (int mt = 0; mt < 4; mt++) {
#pragma unroll
        for (int nt = 0; nt < 4; nt++) {
            const int n = n0 + warp_n * 32 + nt * 8 + c2;
            const float bv0 = addb ? __ldg(bp + n) : 0.f;
            const float bv1 = addb ? __ldg(bp + n + 1) : 0.f;
#pragma unroll
            for (int h = 0; h < 2; h++) {
                const int m = m0 + warp_m * 64 + mt * 16 + g + h * 8;
                if (m >= cnt) continue;
                float v0 = acc[mt][nt][h * 2 + 0] + bv0;
                float v1 = acc[mt][nt][h * 2 + 1] + bv1;
                if (IS_G1) {
                    v0 = fmaxf(v0, 0.f); v1 = fmaxf(v1, 0.f);
                    __nv_bfloat162 h2 = __floats2bfloat162_rn(v0, v1);
                    __nv_bfloat162 l2 = __floats2bfloat162_rn(
                        v0 - __bfloat162float(h2.x), v1 - __bfloat162float(h2.y));
                    const size_t o = (size_t)(off + m) * DH + n;
                    *reinterpret_cast<uint32_t*>(g_h_hi + o) = *reinterpret_cast<uint32_t*>(&h2);
                    *reinterpret_cast<uint32_t*>(g_h_lo + o) = *reinterpret_cast<uint32_t*>(&l2);
                } else {
                    const int tok = g_tokens[off + m];
                    float* orow = out + (size_t)tok * DM + n;
                    atomicAdd(orow, v0);
                    atomicAdd(orow + 1, v1);
                }
            }
        }
    }
}

// ---------------- launch ----------------
extern "C" void kernel_launch(void* const* d_in, const int* in_sizes, int n_in,
                              void* d_out, int out_size) {
    const float* xl = (const float*)d_in[0];
    const float* x0 = (const float*)d_in[1];
    const float* Wg = (const float*)d_in[2];
    const float* W1 = (const float*)d_in[3];
    const float* b1 = (const float*)d_in[4];
    const float* W2 = (const float*)d_in[5];
    const float* b2 = (const float*)d_in[6];
    float* out = (float*)d_out;

    cudaFuncSetAttribute((const void*)k_hmma<DM, DH, true, 1>,
                         cudaFuncAttributeMaxDynamicSharedMemorySize, SMEM_TOTAL);
    cudaFuncSetAttribute((const void*)k_hmma<DH, DM, false, 2>,
                         cudaFuncAttributeMaxDynamicSharedMemorySize, SMEM_TOTAL);

    cudaMemsetAsync(out, 0, (size_t)TOKENS * DM * sizeof(float));
    k_prep<<<dim3(128, 32, 17), dim3(32, 8)>>>(xl, W1, W2);
    k_gating<<<TOKENS / 8, 256>>>(x0, Wg);
    k_scan<<<1, 1>>>();
    k_scatter<<<TOKENS / 256, 256>>>();
    // GEMM1: relu(xl @ W1 + b1) -> h hi/lo
    k_hmma<DM, DH, true, 1><<<dim3(DH / BN, TOKENS / BM, NE), 256, SMEM_TOTAL>>>(b1, nullptr);
    // GEMM2: h @ W2 + b2, split-K=2, atomic combine into out
    k_hmma<DH, DM, false, 2><<<dim3(DM / BN, (TOKENS / BM) * 2, NE), 256, SMEM_TOTAL>>>(b2, out);
}

// round 11
// speedup vs baseline: 1.0276x; 1.0200x over previous
#include <cuda_runtime.h>
#include <cuda_bf16.h>
#include <cstdint>

#define TOKENS 8192
#define DM 1024
#define DH 4096
#define NE 8
#define NSLOTS (TOKENS * 2)

// GEMM tiling: CTA 128x128x32, 8 warps (2m x 4n), warp tile 64x32
// SMEM: XOR-swizzled 64B rows. Stage = 4 tensors * 128 rows * 64B = 32KB; 3 stages -> 2 CTA/SM.
#define BM 128
#define BN 128
#define BK 32
#define NSTG 3
#define OFF_AH 0
#define OFF_AL 8192
#define OFF_BH 16384
#define OFF_BL 24576
#define STAGE_BYTES 32768
#define SMEM_TOTAL (NSTG * STAGE_BYTES)   // 98304 -> 2 CTAs/SM

// ---------------- scratch globals ----------------
__device__ __nv_bfloat16 g_xl_hi[(size_t)TOKENS * DM];
__device__ __nv_bfloat16 g_xl_lo[(size_t)TOKENS * DM];
__device__ __nv_bfloat16 g_w1t_hi[(size_t)NE * DH * DM];   // [E][N=DH][K=DM]
__device__ __nv_bfloat16 g_w1t_lo[(size_t)NE * DH * DM];
__device__ __nv_bfloat16 g_w2t_hi[(size_t)NE * DM * DH];   // [E][N=DM][K=DH]
__device__ __nv_bfloat16 g_w2t_lo[(size_t)NE * DM * DH];
__device__ __nv_bfloat16 g_h_hi[(size_t)NSLOTS * DH];
__device__ __nv_bfloat16 g_h_lo[(size_t)NSLOTS * DH];
__device__ float g_o[(size_t)NSLOTS * DM];
__device__ int g_top2[TOKENS];
__device__ int2 g_slots[TOKENS];
__device__ int g_counts[NE];
__device__ int g_offsets[NE];
__device__ int g_cursor[NE];
__device__ int g_tokens[NSLOTS];

// ---------------- PTX helpers ----------------
__device__ __forceinline__ uint32_t smem_u32(const void* p) {
    uint32_t a;
    asm("{ .reg .u64 t; cvta.to.shared.u64 t, %1; cvt.u32.u64 %0, t; }" : "=r"(a) : "l"(p));
    return a;
}
__device__ __forceinline__ void cp_async16(uint32_t dst, const void* src) {
    asm volatile("cp.async.cg.shared.global [%0], [%1], 16;" :: "r"(dst), "l"(src));
}
__device__ __forceinline__ void cp_commit() { asm volatile("cp.async.commit_group;" ::: "memory"); }
template <int N>
__device__ __forceinline__ void cp_wait() { asm volatile("cp.async.wait_group %0;" :: "n"(N) : "memory"); }

__device__ __forceinline__ void ldsm4(uint32_t* r, uint32_t addr) {
    asm volatile("ldmatrix.sync.aligned.m8n8.x4.shared.b16 {%0,%1,%2,%3}, [%4];"
                 : "=r"(r[0]), "=r"(r[1]), "=r"(r[2]), "=r"(r[3]) : "r"(addr));
}
__device__ __forceinline__ void mma_bf16(float* c, const uint32_t* a, const uint32_t* b) {
    asm volatile(
        "mma.sync.aligned.m16n8k16.row.col.f32.bf16.bf16.f32 "
        "{%0,%1,%2,%3}, {%4,%5,%6,%7}, {%8,%9}, {%0,%1,%2,%3};"
        : "+f"(c[0]), "+f"(c[1]), "+f"(c[2]), "+f"(c[3])
        : "r"(a[0]), "r"(a[1]), "r"(a[2]), "r"(a[3]), "r"(b[0]), "r"(b[1]));
}

// swizzled offset within a 128x64B tile: row r (0..127), 16B chunk c (0..3)
__device__ __forceinline__ uint32_t swz(int r, int c) {
    return (uint32_t)r * 64u + (uint32_t)((c ^ ((r >> 1) & 3)) << 4);
}

// ---------------- kernel 1: cvt xl -> bf16 hi/lo (vectorized) + reset counters ----------------
__global__ void k_cvt_x(const float* __restrict__ x) {
    if (blockIdx.x == 0 && threadIdx.x < NE) g_counts[threadIdx.x] = 0;
    const size_t total4 = (size_t)TOKENS * DM / 4;
    const size_t stride = (size_t)gridDim.x * blockDim.x;
    for (size_t i = (size_t)blockIdx.x * blockDim.x + threadIdx.x; i < total4; i += stride) {
        float4 v = *reinterpret_cast<const float4*>(x + i * 4);
        __nv_bfloat162 h01 = __floats2bfloat162_rn(v.x, v.y);
        __nv_bfloat162 h23 = __floats2bfloat162_rn(v.z, v.w);
        __nv_bfloat162 l01 = __floats2bfloat162_rn(v.x - __bfloat162float(h01.x),
                                                   v.y - __bfloat162float(h01.y));
        __nv_bfloat162 l23 = __floats2bfloat162_rn(v.z - __bfloat162float(h23.x),
                                                   v.w - __bfloat162float(h23.y));
        uint2 hv = make_uint2(*(uint32_t*)&h01, *(uint32_t*)&h23);
        uint2 lv = make_uint2(*(uint32_t*)&l01, *(uint32_t*)&l23);
        *reinterpret_cast<uint2*>(g_xl_hi + i * 4) = hv;
        *reinterpret_cast<uint2*>(g_xl_lo + i * 4) = lv;
    }
}

// ---------------- kernel 2: transpose-convert W[e][k][n] -> O[e][n][k] bf16 hi/lo ----------
// 64(k) x 32(n) tiles; packed bf16x2 stores -> full 128B store transactions per warp.
// Output arrays selected IN DEVICE CODE (device globals must not be passed from host).
template <int K, int N, bool IS_W2>
__global__ void k_wt(const float* __restrict__ W) {
    __shared__ float t[64][33];
    __nv_bfloat16* __restrict__ Ohi = IS_W2 ? g_w2t_hi : g_w1t_hi;
    __nv_bfloat16* __restrict__ Olo = IS_W2 ? g_w2t_lo : g_w1t_lo;
    const int e = blockIdx.z;
    const int n0 = blockIdx.x * 32, k0 = blockIdx.y * 64;
    const float* Wp = W + (size_t)e * K * N;
    const int tx = threadIdx.x, ty = threadIdx.y;   // 32 x 8
#pragma unroll
    for (int j = 0; j < 8; j++)
        t[ty + j * 8][tx] = Wp[(size_t)(k0 + ty + j * 8) * N + n0 + tx];
    __syncthreads();
    // warp ty handles n-local = ty + j*8; lane packs k-local {2*tx, 2*tx+1}
#pragma unroll
    for (int j = 0; j < 4; j++) {
        const int nl = ty + j * 8;
        float v0 = t[tx * 2][nl];
        float v1 = t[tx * 2 + 1][nl];
        __nv_bfloat162 h2 = __floats2bfloat162_rn(v0, v1);
        __nv_bfloat162 l2 = __floats2bfloat162_rn(v0 - __bfloat162float(h2.x),
                                                  v1 - __bfloat162float(h2.y));
        const size_t o = ((size_t)e * N + n0 + nl) * K + k0 + tx * 2;
        *reinterpret_cast<uint32_t*>(Ohi + o) = *reinterpret_cast<uint32_t*>(&h2);
        *reinterpret_cast<uint32_t*>(Olo + o) = *reinterpret_cast<uint32_t*>(&l2);
    }
}

// ---------------- kernel 3: gating (top-2 per token, fp64 accumulate) ----------------
__global__ void k_gating(const float* __restrict__ x0, const float* __restrict__ Wg) {
    const int warp = threadIdx.x >> 5, lane = threadIdx.x & 31;
    const int t = blockIdx.x * (blockDim.x >> 5) + warp;
    double acc[NE];
#pragma unroll
    for (int e = 0; e < NE; e++) acc[e] = 0.0;
    const float* x = x0 + (size_t)t * DM;
    for (int k = lane; k < DM; k += 32) {
        float xv = x[k];
        const float4 w0 = *reinterpret_cast<const float4*>(Wg + (size_t)k * NE);
        const float4 w1 = *reinterpret_cast<const float4*>(Wg + (size_t)k * NE + 4);
        acc[0] += (double)xv * w0.x; acc[1] += (double)xv * w0.y;
        acc[2] += (double)xv * w0.z; acc[3] += (double)xv * w0.w;
        acc[4] += (double)xv * w1.x; acc[5] += (double)xv * w1.y;
        acc[6] += (double)xv * w1.z; acc[7] += (double)xv * w1.w;
    }
#pragma unroll
    for (int off = 16; off > 0; off >>= 1)
#pragma unroll
        for (int e = 0; e < NE; e++) acc[e] += __shfl_xor_sync(0xffffffffu, acc[e], off);
    if (lane == 0) {
        int i1 = 0; double v1 = acc[0];
#pragma unroll
        for (int e = 1; e < NE; e++) if (acc[e] > v1) { v1 = acc[e]; i1 = e; }
        int i2 = -1; double v2 = -1.0e300;
#pragma unroll
        for (int e = 0; e < NE; e++) if (e != i1 && acc[e] > v2) { v2 = acc[e]; i2 = e; }
        g_top2[t] = i1 | (i2 << 8);
        atomicAdd(&g_counts[i1], 1);
        atomicAdd(&g_counts[i2], 1);
    }
}

// ---------------- kernel 4: scan (tiny) ----------------
__global__ void k_scan() {
    int s = 0;
    for (int e = 0; e < NE; e++) { g_offsets[e] = s; g_cursor[e] = s; s += g_counts[e]; }
}

// ---------------- kernel 5: parallel scatter ----------------
__global__ void k_scatter() {
    const int t = blockIdx.x * blockDim.x + threadIdx.x;
    const int p = g_top2[t];
    const int s1 = atomicAdd(&g_cursor[p & 0xff], 1);
    const int s2 = atomicAdd(&g_cursor[(p >> 8) & 0xff], 1);
    g_tokens[s1] = t;
    g_tokens[s2] = t;
    g_slots[t] = make_int2(s1, s2);
}

// ---------------- HMMA GEMM inner loop (R6/R7 winner, unchanged) ----------------
__device__ __forceinline__ void compute_stage(uint32_t st, float acc[4][4][4],
                                              uint32_t aoff, uint32_t boff) {
#pragma unroll
    for (int k16 = 0; k16 < 2; k16++) {
        const uint32_t ab = st + OFF_AH + (aoff ^ (k16 << 5));
        const uint32_t bb = st + OFF_BH + (boff ^ (k16 << 5));
        uint32_t af[4][4], bh[2][4], bl[2][4];
#pragma unroll
        for (int mt = 0; mt < 4; mt++) ldsm4(af[mt], ab + mt * 1024);
#pragma unroll
        for (int p = 0; p < 2; p++)   ldsm4(bh[p], bb + p * 1024);
#pragma unroll
        for (int p = 0; p < 2; p++)   ldsm4(bl[p], bb + (OFF_BL - OFF_BH) + p * 1024);
        // pass 1: Ahi * Bhi
#pragma unroll
        for (int mt = 0; mt < 4; mt++)
#pragma unroll
            for (int nt = 0; nt < 4; nt++)
                mma_bf16(acc[mt][nt], af[mt], &bh[nt >> 1][(nt & 1) * 2]);
        // pass 2: Ahi * Blo
#pragma unroll
        for (int mt = 0; mt < 4; mt++)
#pragma unroll
            for (int nt = 0; nt < 4; nt++)
                mma_bf16(acc[mt][nt], af[mt], &bl[nt >> 1][(nt & 1) * 2]);
        // pass 3: Alo * Bhi (reload A frags from lo tile)
#pragma unroll
        for (int mt = 0; mt < 4; mt++) ldsm4(af[mt], ab + (OFF_AL - OFF_AH) + mt * 1024);
#pragma unroll
        for (int mt = 0; mt < 4; mt++)
#pragma unroll
            for (int nt = 0; nt < 4; nt++)
                mma_bf16(acc[mt][nt], af[mt], &bh[nt >> 1][(nt & 1) * 2]);
    }
}

template <int KT, int NTOT, bool IS_G1>
__global__ __launch_bounds__(256, 2) void k_hmma(const float* __restrict__ bias) {
    const int e = blockIdx.z;
    const int cnt = g_counts[e];
    const int m0 = blockIdx.y * BM;
    if (m0 >= cnt) return;
    const int off = g_offsets[e];
    const int n0 = blockIdx.x * BN;
    const int tid = threadIdx.x;

    extern __shared__ char smem[];
    __shared__ int s_rows[BM];
    const uint32_t sb = smem_u32(smem);

    if (tid < BM) {
        int mm = m0 + tid;
        int mc = mm < cnt ? mm : cnt - 1;
        s_rows[tid] = IS_G1 ? g_tokens[off + mc] : (off + mc);
    }
    __syncthreads();

    const __nv_bfloat16* Ahi = IS_G1 ? g_xl_hi : g_h_hi;
    const __nv_bfloat16* Alo = IS_G1 ? g_xl_lo : g_h_lo;
    const __nv_bfloat16* Bhi = (IS_G1 ? g_w1t_hi : g_w2t_hi) + ((size_t)e * NTOT + n0) * KT;
    const __nv_bfloat16* Blo = (IS_G1 ? g_w1t_lo : g_w2t_lo) + ((size_t)e * NTOT + n0) * KT;

    const int rF = tid >> 2, cF = tid & 3;
    const uint32_t d0 = swz(rF, cF);
    const uint32_t d1 = d0 + 64 * 64;
    const __nv_bfloat16* ah0 = Ahi + (size_t)s_rows[rF] * KT + cF * 8;
    const __nv_bfloat16* al0 = Alo + (size_t)s_rows[rF] * KT + cF * 8;
    const __nv_bfloat16* ah1 = Ahi + (size_t)s_rows[rF + 64] * KT + cF * 8;
    const __nv_bfloat16* al1 = Alo + (size_t)s_rows[rF + 64] * KT + cF * 8;
    const __nv_bfloat16* bh0 = Bhi + (size_t)rF * KT + cF * 8;
    const __nv_bfloat16* bl0 = Blo + (size_t)rF * KT + cF * 8;
    const __nv_bfloat16* bh1 = Bhi + (size_t)(rF + 64) * KT + cF * 8;
    const __nv_bfloat16* bl1 = Blo + (size_t)(rF + 64) * KT + cF * 8;

#define FILL(sidx, k0_) do {                                        \
        uint32_t _s = sb + (sidx) * STAGE_BYTES;                    \
        cp_async16(_s + OFF_AH + d0, ah0 + (k0_));                  \
        cp_async16(_s + OFF_AH + d1, ah1 + (k0_));                  \
        cp_async16(_s + OFF_AL + d0, al0 + (k0_));                  \
        cp_async16(_s + OFF_AL + d1, al1 + (k0_));                  \
        cp_async16(_s + OFF_BH + d0, bh0 + (k0_));                  \
        cp_async16(_s + OFF_BH + d1, bh1 + (k0_));                  \
        cp_async16(_s + OFF_BL + d0, bl0 + (k0_));                  \
        cp_async16(_s + OFF_BL + d1, bl1 + (k0_));                  \
    } while (0)

    const int lane = tid & 31, wid = tid >> 5;
    const int warp_m = wid >> 2, warp_n = wid & 3;
    const int rowA = warp_m * 64 + (lane & 15);
    const int rowB = warp_n * 32 + ((lane >> 4) << 3) + (lane & 7);
    const uint32_t aoff = swz(rowA, lane >> 4);
    const uint32_t boff = swz(rowB, (lane >> 3) & 1);

    float acc[4][4][4];
#pragma unroll
    for (int i = 0; i < 4; i++)
#pragma unroll
        for (int j = 0; j < 4; j++)
#pragma unroll
            for (int q = 0; q < 4; q++) acc[i][j][q] = 0.f;

    constexpr int NKC = KT / BK;
    FILL(0, 0);  cp_commit();
    FILL(1, BK); cp_commit();

    for (int kc = 0; kc < NKC; kc++) {
        cp_wait<1>();
        __syncthreads();
        if (kc + 2 < NKC) { FILL((kc + 2) % NSTG, (kc + 2) * BK); }
        cp_commit();
        compute_stage(sb + (kc % NSTG) * STAGE_BYTES, acc, aoff, boff);
    }
#undef FILL

    // ---- epilogue ----
    const int g = lane >> 2, c2 = (lane & 3) * 2;
    const float* bp = bias + (size_t)e * NTOT;
#pragma unroll
    for (int mt = 0; mt < 4; mt++) {
#pragma unroll
        for (int nt = 0; nt < 4; nt++) {
            const int n = n0 + warp_n * 32 + nt * 8 + c2;
            const float bv0 = __ldg(bp + n), bv1 = __ldg(bp + n + 1);
#pragma unroll
            for (int h = 0; h < 2; h++) {
                const int m = m0 + warp_m * 64 + mt * 16 + g + h * 8;
                if (m >= cnt) continue;
                float v0 = acc[mt][nt][h * 2 + 0] + bv0;
                float v1 = acc[mt][nt][h * 2 + 1] + bv1;
                if (IS_G1) {
                    v0 = fmaxf(v0, 0.f); v1 = fmaxf(v1, 0.f);
                    __nv_bfloat162 h2 = __floats2bfloat162_rn(v0, v1);
                    __nv_bfloat162 l2 = __floats2bfloat162_rn(
                        v0 - __bfloat162float(h2.x), v1 - __bfloat162float(h2.y));
                    const size_t o = (size_t)(off + m) * DH + n;
                    *reinterpret_cast<uint32_t*>(g_h_hi + o) = *reinterpret_cast<uint32_t*>(&h2);
                    *reinterpret_cast<uint32_t*>(g_h_lo + o) = *reinterpret_cast<uint32_t*>(&l2);
                } else {
                    float2 v = make_float2(v0, v1);
                    *reinterpret_cast<float2*>(g_o + (size_t)(off + m) * DM + n) = v;
                }
            }
        }
    }
}

// ---------------- kernel 8: combine out[t] = g_o[s1] + g_o[s2] ----------------
__global__ void k_combine(float* __restrict__ out) {
    const int i = blockIdx.x * blockDim.x + threadIdx.x;   // float4 index
    const int t = i >> 8, cc = i & 255;
    const int2 s = g_slots[t];
    const float4 a = *reinterpret_cast<const float4*>(g_o + (size_t)s.x * DM + cc * 4);
    const float4 b = *reinterpret_cast<const float4*>(g_o + (size_t)s.y * DM + cc * 4);
    float4 r = make_float4(a.x + b.x, a.y + b.y, a.z + b.z, a.w + b.w);
    *reinterpret_cast<float4*>(out + (size_t)t * DM + cc * 4) = r;
}

// ---------------- launch ----------------
extern "C" void kernel_launch(void* const* d_in, const int* in_sizes, int n_in,
                              void* d_out, int out_size) {
    const float* xl = (const float*)d_in[0];
    const float* x0 = (const float*)d_in[1];
    const float* Wg = (const float*)d_in[2];
    const float* W1 = (const float*)d_in[3];
    const float* b1 = (const float*)d_in[4];
    const float* W2 = (const float*)d_in[5];
    const float* b2 = (const float*)d_in[6];
    float* out = (float*)d_out;

    cudaFuncSetAttribute((const void*)k_hmma<DM, DH, true>,
                         cudaFuncAttributeMaxDynamicSharedMemorySize, SMEM_TOTAL);
    cudaFuncSetAttribute((const void*)k_hmma<DH, DM, false>,
                         cudaFuncAttributeMaxDynamicSharedMemorySize, SMEM_TOTAL);

    k_cvt_x<<<512, 256>>>(xl);
    k_wt<DM, DH, false><<<dim3(DH / 32, DM / 64, NE), dim3(32, 8)>>>(W1);
    k_wt<DH, DM, true><<<dim3(DM / 32, DH / 64, NE), dim3(32, 8)>>>(W2);
    k_gating<<<TOKENS / 8, 256>>>(x0, Wg);
    k_scan<<<1, 1>>>();
    k_scatter<<<TOKENS / 256, 256>>>();
    k_hmma<DM, DH, true><<<dim3(DH / BN, TOKENS / BM, NE), 256, SMEM_TOTAL>>>(b1);
    k_hmma<DH, DM, false><<<dim3(DM / BN, TOKENS / BM, NE), 256, SMEM_TOTAL>>>(b2);
    k_combine<<<(TOKENS * DM / 4) / 256, 256>>>(out);
}

// round 12
// speedup vs baseline: 1.1511x; 1.1202x over previous
#include <cuda_runtime.h>
#include <cuda_bf16.h>
#include <cstdint>

#define TOKENS 8192
#define DM 1024
#define DH 4096
#define NE 8
#define NSLOTS (TOKENS * 2)

// GEMM tiling: CTA 128x128x32, 8 warps (2m x 4n), warp tile 64x32
// SMEM: XOR-swizzled 64B rows. Stage = 4 tensors * 128 rows * 64B = 32KB; 3 stages -> 2 CTA/SM.
#define BM 128
#define BN 128
#define BK 32
#define NSTG 3
#define OFF_AH 0
#define OFF_AL 8192
#define OFF_BH 16384
#define OFF_BL 24576
#define STAGE_BYTES 32768
#define SMEM_TOTAL (NSTG * STAGE_BYTES)   // 98304 -> 2 CTAs/SM

// ---------------- scratch globals ----------------
__device__ __nv_bfloat16 g_xl_hi[(size_t)TOKENS * DM];
__device__ __nv_bfloat16 g_xl_lo[(size_t)TOKENS * DM];
__device__ __nv_bfloat16 g_w1t_hi[(size_t)NE * DH * DM];   // [E][N=DH][K=DM]
__device__ __nv_bfloat16 g_w1t_lo[(size_t)NE * DH * DM];
__device__ __nv_bfloat16 g_w2t_hi[(size_t)NE * DM * DH];   // [E][N=DM][K=DH]
__device__ __nv_bfloat16 g_w2t_lo[(size_t)NE * DM * DH];
__device__ __nv_bfloat16 g_h_hi[(size_t)NSLOTS * DH];
__device__ __nv_bfloat16 g_h_lo[(size_t)NSLOTS * DH];
__device__ float g_o[(size_t)NSLOTS * DM];
__device__ int g_top2[TOKENS];
__device__ int2 g_slots[TOKENS];
__device__ int g_counts[NE];
__device__ int g_offsets[NE];
__device__ int g_cursor[NE];
__device__ int g_tokens[NSLOTS];

// ---------------- PTX helpers ----------------
__device__ __forceinline__ uint32_t smem_u32(const void* p) {
    uint32_t a;
    asm("{ .reg .u64 t; cvta.to.shared.u64 t, %1; cvt.u32.u64 %0, t; }" : "=r"(a) : "l"(p));
    return a;
}
__device__ __forceinline__ void cp_async16(uint32_t dst, const void* src) {
    asm volatile("cp.async.cg.shared.global [%0], [%1], 16;" :: "r"(dst), "l"(src));
}
__device__ __forceinline__ void cp_commit() { asm volatile("cp.async.commit_group;" ::: "memory"); }
template <int N>
__device__ __forceinline__ void cp_wait() { asm volatile("cp.async.wait_group %0;" :: "n"(N) : "memory"); }

__device__ __forceinline__ void ldsm4(uint32_t* r, uint32_t addr) {
    asm volatile("ldmatrix.sync.aligned.m8n8.x4.shared.b16 {%0,%1,%2,%3}, [%4];"
                 : "=r"(r[0]), "=r"(r[1]), "=r"(r[2]), "=r"(r[3]) : "r"(addr));
}
__device__ __forceinline__ void mma_bf16(float* c, const uint32_t* a, const uint32_t* b) {
    asm volatile(
        "mma.sync.aligned.m16n8k16.row.col.f32.bf16.bf16.f32 "
        "{%0,%1,%2,%3}, {%4,%5,%6,%7}, {%8,%9}, {%0,%1,%2,%3};"
        : "+f"(c[0]), "+f"(c[1]), "+f"(c[2]), "+f"(c[3])
        : "r"(a[0]), "r"(a[1]), "r"(a[2]), "r"(a[3]), "r"(b[0]), "r"(b[1]));
}

// swizzled offset within a 128x64B tile: row r (0..127), 16B chunk c (0..3)
__device__ __forceinline__ uint32_t swz(int r, int c) {
    return (uint32_t)r * 64u + (uint32_t)((c ^ ((r >> 1) & 3)) << 4);
}

// compensated accumulate: (s,c) += x*w with product error captured via FMA
__device__ __forceinline__ void comp_fma(float& s, float& c, float x, float w) {
    float p = x * w;
    float perr = fmaf(x, w, -p);            // exact product residual
    float t = s + p;
    float z = t - s;
    float serr = (s - (t - z)) + (p - z);   // Neumaier two-sum residual
    s = t;
    c += perr + serr;
}
// merge two compensated partials (a into s/c)
__device__ __forceinline__ void comp_merge(float& s, float& c, float s2, float c2) {
    float t = s + s2;
    float z = t - s;
    float serr = (s - (t - z)) + (s2 - z);
    s = t;
    c += c2 + serr;
}

// ---------------- gating (top-2 per token, compensated fp32) ----------------
__global__ void k_gating(const float* __restrict__ x0, const float* __restrict__ Wg) {
    const int warp = threadIdx.x >> 5, lane = threadIdx.x & 31;
    const int t = blockIdx.x * (blockDim.x >> 5) + warp;
    float s[NE], c[NE];
#pragma unroll
    for (int e = 0; e < NE; e++) { s[e] = 0.f; c[e] = 0.f; }
    const float* x = x0 + (size_t)t * DM;
    for (int k = lane; k < DM; k += 32) {
        float xv = x[k];
        const float4 w0 = *reinterpret_cast<const float4*>(Wg + (size_t)k * NE);
        const float4 w1 = *reinterpret_cast<const float4*>(Wg + (size_t)k * NE + 4);
        comp_fma(s[0], c[0], xv, w0.x); comp_fma(s[1], c[1], xv, w0.y);
        comp_fma(s[2], c[2], xv, w0.z); comp_fma(s[3], c[3], xv, w0.w);
        comp_fma(s[4], c[4], xv, w1.x); comp_fma(s[5], c[5], xv, w1.y);
        comp_fma(s[6], c[6], xv, w1.z); comp_fma(s[7], c[7], xv, w1.w);
    }
#pragma unroll
    for (int off = 16; off > 0; off >>= 1)
#pragma unroll
        for (int e = 0; e < NE; e++) {
            float s2 = __shfl_xor_sync(0xffffffffu, s[e], off);
            float c2 = __shfl_xor_sync(0xffffffffu, c[e], off);
            comp_merge(s[e], c[e], s2, c2);
        }
    if (lane == 0) {
        double acc[NE];
#pragma unroll
        for (int e = 0; e < NE; e++) acc[e] = (double)s[e] + (double)c[e];
        int i1 = 0; double v1 = acc[0];
#pragma unroll
        for (int e = 1; e < NE; e++) if (acc[e] > v1) { v1 = acc[e]; i1 = e; }
        int i2 = -1; double v2 = -1.0e300;
#pragma unroll
        for (int e = 0; e < NE; e++) if (e != i1 && acc[e] > v2) { v2 = acc[e]; i2 = e; }
        g_top2[t] = i1 | (i2 << 8);
        atomicAdd(&g_counts[i1], 1);
        atomicAdd(&g_counts[i2], 1);
    }
}

// ---------------- cvt xl -> bf16 hi/lo (vectorized) ----------------
__global__ void k_cvt_x(const float* __restrict__ x) {
    const size_t total4 = (size_t)TOKENS * DM / 4;
    const size_t stride = (size_t)gridDim.x * blockDim.x;
    for (size_t i = (size_t)blockIdx.x * blockDim.x + threadIdx.x; i < total4; i += stride) {
        float4 v = *reinterpret_cast<const float4*>(x + i * 4);
        __nv_bfloat162 h01 = __floats2bfloat162_rn(v.x, v.y);
        __nv_bfloat162 h23 = __floats2bfloat162_rn(v.z, v.w);
        __nv_bfloat162 l01 = __floats2bfloat162_rn(v.x - __bfloat162float(h01.x),
                                                   v.y - __bfloat162float(h01.y));
        __nv_bfloat162 l23 = __floats2bfloat162_rn(v.z - __bfloat162float(h23.x),
                                                   v.w - __bfloat162float(h23.y));
        uint2 hv = make_uint2(*(uint32_t*)&h01, *(uint32_t*)&h23);
        uint2 lv = make_uint2(*(uint32_t*)&l01, *(uint32_t*)&l23);
        *reinterpret_cast<uint2*>(g_xl_hi + i * 4) = hv;
        *reinterpret_cast<uint2*>(g_xl_lo + i * 4) = lv;
    }
}

// ---------------- transpose-convert W[e][k][n] -> O[e][n][k] bf16 hi/lo ----------
// 64(k) x 32(n) tiles; packed bf16x2 -> full 128B store transactions per warp.
template <int K, int N, bool IS_W2>
__global__ void k_wt(const float* __restrict__ W) {
    __shared__ float t[64][33];
    __nv_bfloat16* __restrict__ Ohi = IS_W2 ? g_w2t_hi : g_w1t_hi;
    __nv_bfloat16* __restrict__ Olo = IS_W2 ? g_w2t_lo : g_w1t_lo;
    const int e = blockIdx.z;
    const int n0 = blockIdx.x * 32, k0 = blockIdx.y * 64;
    const float* Wp = W + (size_t)e * K * N;
    const int tx = threadIdx.x, ty = threadIdx.y;   // 32 x 8
#pragma unroll
    for (int j = 0; j < 8; j++)
        t[ty + j * 8][tx] = Wp[(size_t)(k0 + ty + j * 8) * N + n0 + tx];
    __syncthreads();
#pragma unroll
    for (int j = 0; j < 4; j++) {
        const int nl = ty + j * 8;
        float v0 = t[tx * 2][nl];
        float v1 = t[tx * 2 + 1][nl];
        __nv_bfloat162 h2 = __floats2bfloat162_rn(v0, v1);
        __nv_bfloat162 l2 = __floats2bfloat162_rn(v0 - __bfloat162float(h2.x),
                                                  v1 - __bfloat162float(h2.y));
        const size_t o = ((size_t)e * N + n0 + nl) * K + k0 + tx * 2;
        *reinterpret_cast<uint32_t*>(Ohi + o) = *reinterpret_cast<uint32_t*>(&h2);
        *reinterpret_cast<uint32_t*>(Olo + o) = *reinterpret_cast<uint32_t*>(&l2);
    }
}

// ---------------- counter reset ----------------
__global__ void k_reset() { if (threadIdx.x < NE) g_counts[threadIdx.x] = 0; }

// ---------------- scan (tiny) ----------------
__global__ void k_scan() {
    int s = 0;
    for (int e = 0; e < NE; e++) { g_offsets[e] = s; g_cursor[e] = s; s += g_counts[e]; }
}

// ---------------- parallel scatter ----------------
__global__ void k_scatter() {
    const int t = blockIdx.x * blockDim.x + threadIdx.x;
    const int p = g_top2[t];
    const int s1 = atomicAdd(&g_cursor[p & 0xff], 1);
    const int s2 = atomicAdd(&g_cursor[(p >> 8) & 0xff], 1);
    g_tokens[s1] = t;
    g_tokens[s2] = t;
    g_slots[t] = make_int2(s1, s2);
}

// ---------------- HMMA GEMM inner loop (R6/R7 winner, unchanged) ----------------
__device__ __forceinline__ void compute_stage(uint32_t st, float acc[4][4][4],
                                              uint32_t aoff, uint32_t boff) {
#pragma unroll
    for (int k16 = 0; k16 < 2; k16++) {
        const uint32_t ab = st + OFF_AH + (aoff ^ (k16 << 5));
        const uint32_t bb = st + OFF_BH + (boff ^ (k16 << 5));
        uint32_t af[4][4], bh[2][4], bl[2][4];
#pragma unroll
        for (int mt = 0; mt < 4; mt++) ldsm4(af[mt], ab + mt * 1024);
#pragma unroll
        for (int p = 0; p < 2; p++)   ldsm4(bh[p], bb + p * 1024);
#pragma unroll
        for (int p = 0; p < 2; p++)   ldsm4(bl[p], bb + (OFF_BL - OFF_BH) + p * 1024);
        // pass 1: Ahi * Bhi
#pragma unroll
        for (int mt = 0; mt < 4; mt++)
#pragma unroll
            for (int nt = 0; nt < 4; nt++)
                mma_bf16(acc[mt][nt], af[mt], &bh[nt >> 1][(nt & 1) * 2]);
        // pass 2: Ahi * Blo
#pragma unroll
        for (int mt = 0; mt < 4; mt++)
#pragma unroll
            for (int nt = 0; nt < 4; nt++)
                mma_bf16(acc[mt][nt], af[mt], &bl[nt >> 1][(nt & 1) * 2]);
        // pass 3: Alo * Bhi (reload A frags from lo tile)
#pragma unroll
        for (int mt = 0; mt < 4; mt++) ldsm4(af[mt], ab + (OFF_AL - OFF_AH) + mt * 1024);
#pragma unroll
        for (int mt = 0; mt < 4; mt++)
#pragma unroll
            for (int nt = 0; nt < 4; nt++)
                mma_bf16(acc[mt][nt], af[mt], &bh[nt >> 1][(nt & 1) * 2]);
    }
}

template <int KT, int NTOT, bool IS_G1>
__global__ __launch_bounds__(256, 2) void k_hmma(const float* __restrict__ bias) {
    const int e = blockIdx.z;
    const int cnt = g_counts[e];
    const int m0 = blockIdx.y * BM;
    if (m0 >= cnt) return;
    const int off = g_offsets[e];
    const int n0 = blockIdx.x * BN;
    const int tid = threadIdx.x;

    extern __shared__ char smem[];
    __shared__ int s_rows[BM];
    const uint32_t sb = smem_u32(smem);

    if (tid < BM) {
        int mm = m0 + tid;
        int mc = mm < cnt ? mm : cnt - 1;
        s_rows[tid] = IS_G1 ? g_tokens[off + mc] : (off + mc);
    }
    __syncthreads();

    const __nv_bfloat16* Ahi = IS_G1 ? g_xl_hi : g_h_hi;
    const __nv_bfloat16* Alo = IS_G1 ? g_xl_lo : g_h_lo;
    const __nv_bfloat16* Bhi = (IS_G1 ? g_w1t_hi : g_w2t_hi) + ((size_t)e * NTOT + n0) * KT;
    const __nv_bfloat16* Blo = (IS_G1 ? g_w1t_lo : g_w2t_lo) + ((size_t)e * NTOT + n0) * KT;

    const int rF = tid >> 2, cF = tid & 3;
    const uint32_t d0 = swz(rF, cF);
    const uint32_t d1 = d0 + 64 * 64;
    const __nv_bfloat16* ah0 = Ahi + (size_t)s_rows[rF] * KT + cF * 8;
    const __nv_bfloat16* al0 = Alo + (size_t)s_rows[rF] * KT + cF * 8;
    const __nv_bfloat16* ah1 = Ahi + (size_t)s_rows[rF + 64] * KT + cF * 8;
    const __nv_bfloat16* al1 = Alo + (size_t)s_rows[rF + 64] * KT + cF * 8;
    const __nv_bfloat16* bh0 = Bhi + (size_t)rF * KT + cF * 8;
    const __nv_bfloat16* bl0 = Blo + (size_t)rF * KT + cF * 8;
    const __nv_bfloat16* bh1 = Bhi + (size_t)(rF + 64) * KT + cF * 8;
    const __nv_bfloat16* bl1 = Blo + (size_t)(rF + 64) * KT + cF * 8;

#define FILL(sidx, k0_) do {                                        \
        uint32_t _s = sb + (sidx) * STAGE_BYTES;                    \
        cp_async16(_s + OFF_AH + d0, ah0 + (k0_));                  \
        cp_async16(_s + OFF_AH + d1, ah1 + (k0_));                  \
        cp_async16(_s + OFF_AL + d0, al0 + (k0_));                  \
        cp_async16(_s + OFF_AL + d1, al1 + (k0_));                  \
        cp_async16(_s + OFF_BH + d0, bh0 + (k0_));                  \
        cp_async16(_s + OFF_BH + d1, bh1 + (k0_));                  \
        cp_async16(_s + OFF_BL + d0, bl0 + (k0_));                  \
        cp_async16(_s + OFF_BL + d1, bl1 + (k0_));                  \
    } while (0)

    const int lane = tid & 31, wid = tid >> 5;
    const int warp_m = wid >> 2, warp_n = wid & 3;
    const int rowA = warp_m * 64 + (lane & 15);
    const int rowB = warp_n * 32 + ((lane >> 4) << 3) + (lane & 7);
    const uint32_t aoff = swz(rowA, lane >> 4);
    const uint32_t boff = swz(rowB, (lane >> 3) & 1);

    float acc[4][4][4];
#pragma unroll
    for (int i = 0; i < 4; i++)
#pragma unroll
        for (int j = 0; j < 4; j++)
#pragma unroll
            for (int q = 0; q < 4; q++) acc[i][j][q] = 0.f;

    constexpr int NKC = KT / BK;
    FILL(0, 0);  cp_commit();
    FILL(1, BK); cp_commit();

    for (int kc = 0; kc < NKC; kc++) {
        cp_wait<1>();
        __syncthreads();
        if (kc + 2 < NKC) { FILL((kc + 2) % NSTG, (kc + 2) * BK); }
        cp_commit();
        compute_stage(sb + (kc % NSTG) * STAGE_BYTES, acc, aoff, boff);
    }
#undef FILL

    // ---- epilogue ----
    const int g = lane >> 2, c2 = (lane & 3) * 2;
    const float* bp = bias + (size_t)e * NTOT;
#pragma unroll
    for (int mt = 0; mt < 4; mt++) {
#pragma unroll
        for (int nt = 0; nt < 4; nt++) {
            const int n = n0 + warp_n * 32 + nt * 8 + c2;
            const float bv0 = __ldg(bp + n), bv1 = __ldg(bp + n + 1);
#pragma unroll
            for (int h = 0; h < 2; h++) {
                const int m = m0 + warp_m * 64 + mt * 16 + g + h * 8;
                if (m >= cnt) continue;
                float v0 = acc[mt][nt][h * 2 + 0] + bv0;
                float v1 = acc[mt][nt][h * 2 + 1] + bv1;
                if (IS_G1) {
                    v0 = fmaxf(v0, 0.f); v1 = fmaxf(v1, 0.f);
                    __nv_bfloat162 h2 = __floats2bfloat162_rn(v0, v1);
                    __nv_bfloat162 l2 = __floats2bfloat162_rn(
                        v0 - __bfloat162float(h2.x), v1 - __bfloat162float(h2.y));
                    const size_t o = (size_t)(off + m) * DH + n;
                    *reinterpret_cast<uint32_t*>(g_h_hi + o) = *reinterpret_cast<uint32_t*>(&h2);
                    *reinterpret_cast<uint32_t*>(g_h_lo + o) = *reinterpret_cast<uint32_t*>(&l2);
                } else {
                    float2 v = make_float2(v0, v1);
                    *reinterpret_cast<float2*>(g_o + (size_t)(off + m) * DM + n) = v;
                }
            }
        }
    }
}

// ---------------- combine out[t] = g_o[s1] + g_o[s2] ----------------
__global__ void k_combine(float* __restrict__ out) {
    const int i = blockIdx.x * blockDim.x + threadIdx.x;   // float4 index
    const int t = i >> 8, cc = i & 255;
    const int2 s = g_slots[t];
    const float4 a = *reinterpret_cast<const float4*>(g_o + (size_t)s.x * DM + cc * 4);
    const float4 b = *reinterpret_cast<const float4*>(g_o + (size_t)s.y * DM + cc * 4);
    float4 r = make_float4(a.x + b.x, a.y + b.y, a.z + b.z, a.w + b.w);
    *reinterpret_cast<float4*>(out + (size_t)t * DM + cc * 4) = r;
}

// ---------------- launch ----------------
extern "C" void kernel_launch(void* const* d_in, const int* in_sizes, int n_in,
                              void* d_out, int out_size) {
    const float* xl = (const float*)d_in[0];
    const float* x0 = (const float*)d_in[1];
    const float* Wg = (const float*)d_in[2];
    const float* W1 = (const float*)d_in[3];
    const float* b1 = (const float*)d_in[4];
    const float* W2 = (const float*)d_in[5];
    const float* b2 = (const float*)d_in[6];
    float* out = (float*)d_out;

    cudaFuncSetAttribute((const void*)k_hmma<DM, DH, true>,
                         cudaFuncAttributeMaxDynamicSharedMemorySize, SMEM_TOTAL);
    cudaFuncSetAttribute((const void*)k_hmma<DH, DM, false>,
                         cudaFuncAttributeMaxDynamicSharedMemorySize, SMEM_TOTAL);

    k_reset<<<1, 32>>>();
    k_gating<<<TOKENS / 8, 256>>>(x0, Wg);
    k_cvt_x<<<512, 256>>>(xl);
    k_wt<DH, DM, true><<<dim3(DM / 32, DH / 64, NE), dim3(32, 8)>>>(W2);   // profiled slot (4th)
    k_wt<DM, DH, false><<<dim3(DH / 32, DM / 64, NE), dim3(32, 8)>>>(W1);
    k_scan<<<1, 1>>>();
    k_scatter<<<TOKENS / 256, 256>>>();
    k_hmma<DM, DH, true><<<dim3(DH / BN, TOKENS / BM, NE), 256, SMEM_TOTAL>>>(b1);
    k_hmma<DH, DM, false><<<dim3(DM / BN, TOKENS / BM, NE), 256, SMEM_TOTAL>>>(b2);
    k_combine<<<(TOKENS * DM / 4) / 256, 256>>>(out);
}

// round 13
// speedup vs baseline: 1.3379x; 1.1623x over previous
#include <cuda_runtime.h>
#include <cuda_bf16.h>
#include <cuda_fp16.h>
#include <cstdint>

#define TOKENS 8192
#define DM 1024
#define DH 4096
#define NE 8
#define NSLOTS (TOKENS * 2)

// GEMM tiling: CTA 128x128x32, 8 warps (2m x 4n), warp tile 64x32
// SMEM: XOR-swizzled 64B rows. GEMM1 stage = 3 tensors (AH,AL,BH) = 24KB;
// GEMM2 stage = 4 tensors = 32KB. 3 stages, 2 CTAs/SM either way.
#define BM 128
#define BN 128
#define BK 32
#define NSTG 3
#define O_AL 8192
#define O_BH 16384
#define O_BL 24576

// ---------------- scratch globals (fp16 hi/lo) ----------------
__device__ __half g_xl_hi[(size_t)TOKENS * DM];
__device__ __half g_xl_lo[(size_t)TOKENS * DM];
__device__ __half g_w1t_hi[(size_t)NE * DH * DM];   // [E][N=DH][K=DM], hi only (2-pass)
__device__ __half g_w2t_hi[(size_t)NE * DM * DH];   // [E][N=DM][K=DH]
__device__ __half g_w2t_lo[(size_t)NE * DM * DH];
__device__ __half g_h_hi[(size_t)NSLOTS * DH];
__device__ __half g_h_lo[(size_t)NSLOTS * DH];
__device__ float g_o[(size_t)NSLOTS * DM];
__device__ int g_top2[TOKENS];
__device__ int2 g_slots[TOKENS];
__device__ int g_counts[NE];
__device__ int g_offsets[NE];
__device__ int g_cursor[NE];
__device__ int g_tokens[NSLOTS];

// ---------------- PTX helpers ----------------
__device__ __forceinline__ uint32_t smem_u32(const void* p) {
    uint32_t a;
    asm("{ .reg .u64 t; cvta.to.shared.u64 t, %1; cvt.u32.u64 %0, t; }" : "=r"(a) : "l"(p));
    return a;
}
__device__ __forceinline__ void cp_async16(uint32_t dst, const void* src) {
    asm volatile("cp.async.cg.shared.global [%0], [%1], 16;" :: "r"(dst), "l"(src));
}
__device__ __forceinline__ void cp_commit() { asm volatile("cp.async.commit_group;" ::: "memory"); }
template <int N>
__device__ __forceinline__ void cp_wait() { asm volatile("cp.async.wait_group %0;" :: "n"(N) : "memory"); }

__device__ __forceinline__ void ldsm4(uint32_t* r, uint32_t addr) {
    asm volatile("ldmatrix.sync.aligned.m8n8.x4.shared.b16 {%0,%1,%2,%3}, [%4];"
                 : "=r"(r[0]), "=r"(r[1]), "=r"(r[2]), "=r"(r[3]) : "r"(addr));
}
__device__ __forceinline__ void mma_fp16(float* c, const uint32_t* a, const uint32_t* b) {
    asm volatile(
        "mma.sync.aligned.m16n8k16.row.col.f32.f16.f16.f32 "
        "{%0,%1,%2,%3}, {%4,%5,%6,%7}, {%8,%9}, {%0,%1,%2,%3};"
        : "+f"(c[0]), "+f"(c[1]), "+f"(c[2]), "+f"(c[3])
        : "r"(a[0]), "r"(a[1]), "r"(a[2]), "r"(a[3]), "r"(b[0]), "r"(b[1]));
}

// swizzled offset within a 128x64B tile: row r (0..127), 16B chunk c (0..3)
__device__ __forceinline__ uint32_t swz(int r, int c) {
    return (uint32_t)r * 64u + (uint32_t)((c ^ ((r >> 1) & 3)) << 4);
}

// pack two floats into half2 bits + residual half2 bits
__device__ __forceinline__ void split2(float v0, float v1, uint32_t& hw, uint32_t& lw) {
    __half2 h2 = __floats2half2_rn(v0, v1);
    __half2 l2 = __floats2half2_rn(v0 - __half2float(__low2half(h2)),
                                   v1 - __half2float(__high2half(h2)));
    hw = *reinterpret_cast<uint32_t*>(&h2);
    lw = *reinterpret_cast<uint32_t*>(&l2);
}

// compensated accumulate: (s,c) += x*w with product error captured via FMA
__device__ __forceinline__ void comp_fma(float& s, float& c, float x, float w) {
    float p = x * w;
    float perr = fmaf(x, w, -p);
    float t = s + p;
    float z = t - s;
    float serr = (s - (t - z)) + (p - z);
    s = t;
    c += perr + serr;
}
__device__ __forceinline__ void comp_merge(float& s, float& c, float s2, float c2) {
    float t = s + s2;
    float z = t - s;
    float serr = (s - (t - z)) + (s2 - z);
    s = t;
    c += c2 + serr;
}

// ---------------- counter reset ----------------
__global__ void k_reset() { if (threadIdx.x < NE) g_counts[threadIdx.x] = 0; }

// ---------------- gating (top-2 per token, compensated fp32) ----------------
__global__ void k_gating(const float* __restrict__ x0, const float* __restrict__ Wg) {
    const int warp = threadIdx.x >> 5, lane = threadIdx.x & 31;
    const int t = blockIdx.x * (blockDim.x >> 5) + warp;
    float s[NE], c[NE];
#pragma unroll
    for (int e = 0; e < NE; e++) { s[e] = 0.f; c[e] = 0.f; }
    const float* x = x0 + (size_t)t * DM;
    for (int k = lane; k < DM; k += 32) {
        float xv = x[k];
        const float4 w0 = *reinterpret_cast<const float4*>(Wg + (size_t)k * NE);
        const float4 w1 = *reinterpret_cast<const float4*>(Wg + (size_t)k * NE + 4);
        comp_fma(s[0], c[0], xv, w0.x); comp_fma(s[1], c[1], xv, w0.y);
        comp_fma(s[2], c[2], xv, w0.z); comp_fma(s[3], c[3], xv, w0.w);
        comp_fma(s[4], c[4], xv, w1.x); comp_fma(s[5], c[5], xv, w1.y);
        comp_fma(s[6], c[6], xv, w1.z); comp_fma(s[7], c[7], xv, w1.w);
    }
#pragma unroll
    for (int off = 16; off > 0; off >>= 1)
#pragma unroll
        for (int e = 0; e < NE; e++) {
            float s2 = __shfl_xor_sync(0xffffffffu, s[e], off);
            float c2 = __shfl_xor_sync(0xffffffffu, c[e], off);
            comp_merge(s[e], c[e], s2, c2);
        }
    if (lane == 0) {
        double acc[NE];
#pragma unroll
        for (int e = 0; e < NE; e++) acc[e] = (double)s[e] + (double)c[e];
        int i1 = 0; double v1 = acc[0];
#pragma unroll
        for (int e = 1; e < NE; e++) if (acc[e] > v1) { v1 = acc[e]; i1 = e; }
        int i2 = -1; double v2 = -1.0e300;
#pragma unroll
        for (int e = 0; e < NE; e++) if (e != i1 && acc[e] > v2) { v2 = acc[e]; i2 = e; }
        g_top2[t] = i1 | (i2 << 8);
        atomicAdd(&g_counts[i1], 1);
        atomicAdd(&g_counts[i2], 1);
    }
}

// ---------------- cvt xl -> fp16 hi/lo (vectorized) ----------------
__global__ void k_cvt_x(const float* __restrict__ x) {
    const size_t total4 = (size_t)TOKENS * DM / 4;
    const size_t stride = (size_t)gridDim.x * blockDim.x;
    for (size_t i = (size_t)blockIdx.x * blockDim.x + threadIdx.x; i < total4; i += stride) {
        float4 v = *reinterpret_cast<const float4*>(x + i * 4);
        uint32_t h01, l01, h23, l23;
        split2(v.x, v.y, h01, l01);
        split2(v.z, v.w, h23, l23);
        *reinterpret_cast<uint2*>(g_xl_hi + i * 4) = make_uint2(h01, h23);
        *reinterpret_cast<uint2*>(g_xl_lo + i * 4) = make_uint2(l01, l23);
    }
}

// ---------------- transpose-convert W[e][k][n] -> O[e][n][k] fp16 ----------
// MODE 0: W1, hi only. MODE 1: W2, hi + lo. 64(k) x 32(n) tiles, packed stores.
template <int K, int N, int MODE>
__global__ void k_wt(const float* __restrict__ W) {
    __shared__ float t[64][33];
    const int e = blockIdx.z;
    const int n0 = blockIdx.x * 32, k0 = blockIdx.y * 64;
    const float* Wp = W + (size_t)e * K * N;
    const int tx = threadIdx.x, ty = threadIdx.y;   // 32 x 8
#pragma unroll
    for (int j = 0; j < 8; j++)
        t[ty + j * 8][tx] = Wp[(size_t)(k0 + ty + j * 8) * N + n0 + tx];
    __syncthreads();
#pragma unroll
    for (int j = 0; j < 4; j++) {
        const int nl = ty + j * 8;
        float v0 = t[tx * 2][nl];
        float v1 = t[tx * 2 + 1][nl];
        const size_t o = ((size_t)e * N + n0 + nl) * K + k0 + tx * 2;
        uint32_t hw, lw;
        split2(v0, v1, hw, lw);
        if (MODE == 0) {
            *reinterpret_cast<uint32_t*>(g_w1t_hi + o) = hw;
        } else {
            *reinterpret_cast<uint32_t*>(g_w2t_hi + o) = hw;
            *reinterpret_cast<uint32_t*>(g_w2t_lo + o) = lw;
        }
    }
}

// ---------------- scan (tiny) ----------------
__global__ void k_scan() {
    int s = 0;
    for (int e = 0; e < NE; e++) { g_offsets[e] = s; g_cursor[e] = s; s += g_counts[e]; }
}

// ---------------- parallel scatter ----------------
__global__ void k_scatter() {
    const int t = blockIdx.x * blockDim.x + threadIdx.x;
    const int p = g_top2[t];
    const int s1 = atomicAdd(&g_cursor[p & 0xff], 1);
    const int s2 = atomicAdd(&g_cursor[(p >> 8) & 0xff], 1);
    g_tokens[s1] = t;
    g_tokens[s2] = t;
    g_slots[t] = make_int2(s1, s2);
}

// ---------------- HMMA pass: 4 m-tiles x 4 n-tiles ----------------
__device__ __forceinline__ void pass(float acc[4][4][4], const uint32_t af[4][4],
                                     const uint32_t b[2][4]) {
#pragma unroll
    for (int mt = 0; mt < 4; mt++)
#pragma unroll
        for (int nt = 0; nt < 4; nt++)
            mma_fp16(acc[mt][nt], af[mt], &b[nt >> 1][(nt & 1) * 2]);
}

template <int KT, int NTOT, bool IS_G1>
__global__ __launch_bounds__(256, 2) void k_hmma(const float* __restrict__ bias) {
    constexpr int STB = IS_G1 ? 24576 : 32768;          // stage bytes
    const int e = blockIdx.z;
    const int cnt = g_counts[e];
    const int m0 = blockIdx.y * BM;
    if (m0 >= cnt) return;
    const int off = g_offsets[e];
    const int n0 = blockIdx.x * BN;
    const int tid = threadIdx.x;

    extern __shared__ char smem[];
    __shared__ int s_rows[BM];
    const uint32_t sb = smem_u32(smem);

    if (tid < BM) {
        int mm = m0 + tid;
        int mc = mm < cnt ? mm : cnt - 1;
        s_rows[tid] = IS_G1 ? g_tokens[off + mc] : (off + mc);
    }
    __syncthreads();

    const __half* Ahi = IS_G1 ? g_xl_hi : g_h_hi;
    const __half* Alo = IS_G1 ? g_xl_lo : g_h_lo;
    const __half* Bhi = (IS_G1 ? g_w1t_hi : g_w2t_hi) + ((size_t)e * NTOT + n0) * KT;
    const __half* Blo = IS_G1 ? nullptr
                              : g_w2t_lo + ((size_t)e * NTOT + n0) * KT;

    const int rF = tid >> 2, cF = tid & 3;
    const uint32_t d0 = swz(rF, cF);
    const uint32_t d1 = d0 + 64 * 64;
    const __half* ah0 = Ahi + (size_t)s_rows[rF] * KT + cF * 8;
    const __half* al0 = Alo + (size_t)s_rows[rF] * KT + cF * 8;
    const __half* ah1 = Ahi + (size_t)s_rows[rF + 64] * KT + cF * 8;
    const __half* al1 = Alo + (size_t)s_rows[rF + 64] * KT + cF * 8;
    const __half* bh0 = Bhi + (size_t)rF * KT + cF * 8;
    const __half* bh1 = Bhi + (size_t)(rF + 64) * KT + cF * 8;
    const __half* bl0 = IS_G1 ? nullptr : Blo + (size_t)rF * KT + cF * 8;
    const __half* bl1 = IS_G1 ? nullptr : Blo + (size_t)(rF + 64) * KT + cF * 8;

#define FILL(sidx, k0_) do {                                        \
        uint32_t _s = sb + (sidx) * STB;                            \
        cp_async16(_s + d0, ah0 + (k0_));                           \
        cp_async16(_s + d1, ah1 + (k0_));                           \
        cp_async16(_s + O_AL + d0, al0 + (k0_));                    \
        cp_async16(_s + O_AL + d1, al1 + (k0_));                    \
        cp_async16(_s + O_BH + d0, bh0 + (k0_));                    \
        cp_async16(_s + O_BH + d1, bh1 + (k0_));                    \
        if (!IS_G1) {                                               \
            cp_async16(_s + O_BL + d0, bl0 + (k0_));                \
            cp_async16(_s + O_BL + d1, bl1 + (k0_));                \
        }                                                           \
    } while (0)

    const int lane = tid & 31, wid = tid >> 5;
    const int warp_m = wid >> 2, warp_n = wid & 3;
    const int rowA = warp_m * 64 + (lane & 15);
    const int rowB = warp_n * 32 + ((lane >> 4) << 3) + (lane & 7);
    const uint32_t aoff = swz(rowA, lane >> 4);
    const uint32_t boff = swz(rowB, (lane >> 3) & 1);

    float acc[4][4][4];
#pragma unroll
    for (int i = 0; i < 4; i++)
#pragma unroll
        for (int j = 0; j < 4; j++)
#pragma unroll
            for (int q = 0; q < 4; q++) acc[i][j][q] = 0.f;

    constexpr int NKC = KT / BK;
    FILL(0, 0);  cp_commit();
    FILL(1, BK); cp_commit();

    for (int kc = 0; kc < NKC; kc++) {
        cp_wait<1>();
        __syncthreads();
        if (kc + 2 < NKC) { FILL((kc + 2) % NSTG, (kc + 2) * BK); }
        cp_commit();
        const uint32_t st = sb + (kc % NSTG) * STB;
#pragma unroll
        for (int k16 = 0; k16 < 2; k16++) {
            const uint32_t ab = st + (aoff ^ (k16 << 5));
            const uint32_t bb = st + O_BH + (boff ^ (k16 << 5));
            uint32_t af[4][4], bh[2][4];
#pragma unroll
            for (int mt = 0; mt < 4; mt++) ldsm4(af[mt], ab + mt * 1024);
#pragma unroll
            for (int p = 0; p < 2; p++)   ldsm4(bh[p], bb + p * 1024);
            if (IS_G1) {
                // 2-pass: (ah + al) * bh — only dropped term is a*bl
                pass(acc, af, bh);
#pragma unroll
                for (int mt = 0; mt < 4; mt++) ldsm4(af[mt], ab + O_AL + mt * 1024);
                pass(acc, af, bh);
            } else {
                // 3-pass: ah*bh + ah*bl + al*bh
                uint32_t bl[2][4];
#pragma unroll
                for (int p = 0; p < 2; p++) ldsm4(bl[p], bb + (O_BL - O_BH) + p * 1024);
                pass(acc, af, bh);
                pass(acc, af, bl);
#pragma unroll
                for (int mt = 0; mt < 4; mt++) ldsm4(af[mt], ab + O_AL + mt * 1024);
                pass(acc, af, bh);
            }
        }
    }
#undef FILL

    // ---- epilogue ----
    const int g = lane >> 2, c2 = (lane & 3) * 2;
    const float* bp = bias + (size_t)e * NTOT;
#pragma unroll
    for (int mt = 0; mt < 4; mt++) {
#pragma unroll
        for (int nt = 0; nt < 4; nt++) {
            const int n = n0 + warp_n * 32 + nt * 8 + c2;
            const float bv0 = __ldg(bp + n), bv1 = __ldg(bp + n + 1);
#pragma unroll
            for (int h = 0; h < 2; h++) {
                const int m = m0 + warp_m * 64 + mt * 16 + g + h * 8;
                if (m >= cnt) continue;
                float v0 = acc[mt][nt][h * 2 + 0] + bv0;
                float v1 = acc[mt][nt][h * 2 + 1] + bv1;
                if (IS_G1) {
                    v0 = fmaxf(v0, 0.f); v1 = fmaxf(v1, 0.f);
                    uint32_t hw, lw;
                    split2(v0, v1, hw, lw);
                    const size_t o = (size_t)(off + m) * DH + n;
                    *reinterpret_cast<uint32_t*>(g_h_hi + o) = hw;
                    *reinterpret_cast<uint32_t*>(g_h_lo + o) = lw;
                } else {
                    float2 v = make_float2(v0, v1);
                    *reinterpret_cast<float2*>(g_o + (size_t)(off + m) * DM + n) = v;
                }
            }
        }
    }
}

// ---------------- combine out[t] = g_o[s1] + g_o[s2] ----------------
__global__ void k_combine(float* __restrict__ out) {
    const int i = blockIdx.x * blockDim.x + threadIdx.x;   // float4 index
    const int t = i >> 8, cc = i & 255;
    const int2 s = g_slots[t];
    const float4 a = *reinterpret_cast<const float4*>(g_o + (size_t)s.x * DM + cc * 4);
    const float4 b = *reinterpret_cast<const float4*>(g_o + (size_t)s.y * DM + cc * 4);
    float4 r = make_float4(a.x + b.x, a.y + b.y, a.z + b.z, a.w + b.w);
    *reinterpret_cast<float4*>(out + (size_t)t * DM + cc * 4) = r;
}

// ---------------- launch ----------------
extern "C" void kernel_launch(void* const* d_in, const int* in_sizes, int n_in,
                              void* d_out, int out_size) {
    const float* xl = (const float*)d_in[0];
    const float* x0 = (const float*)d_in[1];
    const float* Wg = (const float*)d_in[2];
    const float* W1 = (const float*)d_in[3];
    const float* b1 = (const float*)d_in[4];
    const float* W2 = (const float*)d_in[5];
    const float* b2 = (const float*)d_in[6];
    float* out = (float*)d_out;

    cudaFuncSetAttribute((const void*)k_hmma<DM, DH, true>,
                         cudaFuncAttributeMaxDynamicSharedMemorySize, NSTG * 24576);
    cudaFuncSetAttribute((const void*)k_hmma<DH, DM, false>,
                         cudaFuncAttributeMaxDynamicSharedMemorySize, NSTG * 32768);

    k_reset<<<1, 32>>>();
    k_gating<<<TOKENS / 8, 256>>>(x0, Wg);
    k_cvt_x<<<512, 256>>>(xl);
    k_wt<DM, DH, 0><<<dim3(DH / 32, DM / 64, NE), dim3(32, 8)>>>(W1);   // profiled slot
    k_wt<DH, DM, 1><<<dim3(DM / 32, DH / 64, NE), dim3(32, 8)>>>(W2);
    k_scan<<<1, 1>>>();
    k_scatter<<<TOKENS / 256, 256>>>();
    // GEMM1: fp16 2-pass, relu -> h (fp16 hi/lo)
    k_hmma<DM, DH, true><<<dim3(DH / BN, TOKENS / BM, NE), 256, NSTG * 24576>>>(b1);
    // GEMM2: fp16 3-pass -> g_o
    k_hmma<DH, DM, false><<<dim3(DM / BN, TOKENS / BM, NE), 256, NSTG * 32768>>>(b2);
    k_combine<<<(TOKENS * DM / 4) / 256, 256>>>(out);
}

// round 14
// speedup vs baseline: 1.6096x; 1.2031x over previous
#include <cuda_runtime.h>
#include <cuda_bf16.h>
#include <cuda_fp16.h>
#include <cstdint>

#define TOKENS 8192
#define DM 1024
#define DH 4096
#define NE 8
#define NSLOTS (TOKENS * 2)

// GEMM tiling: CTA 128x128x32, 8 warps (2m x 4n), warp tile 64x32, fp16 2-pass.
// SMEM: XOR-swizzled 64B rows. Stage = 3 tensors (AH, AL, BH) = 24KB; 3 stages; 2 CTA/SM.
#define BM 128
#define BN 128
#define BK 32
#define NSTG 3
#define O_AL 8192
#define O_BH 16384
#define STB 24576
#define SMEM_TOTAL (NSTG * STB)   // 73728

// ---------------- scratch globals (fp16 hi/lo) ----------------
__device__ __half g_xl_hi[(size_t)TOKENS * DM];
__device__ __half g_xl_lo[(size_t)TOKENS * DM];
__device__ __half g_w1t_hi[(size_t)NE * DH * DM];   // [E][N=DH][K=DM], hi only
__device__ __half g_w2t_hi[(size_t)NE * DM * DH];   // [E][N=DM][K=DH], hi only
__device__ __half g_h_hi[(size_t)NSLOTS * DH];
__device__ __half g_h_lo[(size_t)NSLOTS * DH];
__device__ float g_o[(size_t)NSLOTS * DM];
__device__ int g_top2[TOKENS];
__device__ int2 g_slots[TOKENS];
__device__ int g_counts[NE];
__device__ int g_offsets[NE];
__device__ int g_cursor[NE];
__device__ int g_tokens[NSLOTS];

// ---------------- PTX helpers ----------------
__device__ __forceinline__ uint32_t smem_u32(const void* p) {
    uint32_t a;
    asm("{ .reg .u64 t; cvta.to.shared.u64 t, %1; cvt.u32.u64 %0, t; }" : "=r"(a) : "l"(p));
    return a;
}
__device__ __forceinline__ void cp_async16(uint32_t dst, const void* src) {
    asm volatile("cp.async.cg.shared.global [%0], [%1], 16;" :: "r"(dst), "l"(src));
}
__device__ __forceinline__ void cp_commit() { asm volatile("cp.async.commit_group;" ::: "memory"); }
template <int N>
__device__ __forceinline__ void cp_wait() { asm volatile("cp.async.wait_group %0;" :: "n"(N) : "memory"); }

__device__ __forceinline__ void ldsm4(uint32_t* r, uint32_t addr) {
    asm volatile("ldmatrix.sync.aligned.m8n8.x4.shared.b16 {%0,%1,%2,%3}, [%4];"
                 : "=r"(r[0]), "=r"(r[1]), "=r"(r[2]), "=r"(r[3]) : "r"(addr));
}
__device__ __forceinline__ void mma_fp16(float* c, const uint32_t* a, const uint32_t* b) {
    asm volatile(
        "mma.sync.aligned.m16n8k16.row.col.f32.f16.f16.f32 "
        "{%0,%1,%2,%3}, {%4,%5,%6,%7}, {%8,%9}, {%0,%1,%2,%3};"
        : "+f"(c[0]), "+f"(c[1]), "+f"(c[2]), "+f"(c[3])
        : "r"(a[0]), "r"(a[1]), "r"(a[2]), "r"(a[3]), "r"(b[0]), "r"(b[1]));
}

// swizzled offset within a 128x64B tile: row r (0..127), 16B chunk c (0..3)
__device__ __forceinline__ uint32_t swz(int r, int c) {
    return (uint32_t)r * 64u + (uint32_t)((c ^ ((r >> 1) & 3)) << 4);
}

// pack two floats into half2 bits + residual half2 bits
__device__ __forceinline__ void split2(float v0, float v1, uint32_t& hw, uint32_t& lw) {
    __half2 h2 = __floats2half2_rn(v0, v1);
    __half2 l2 = __floats2half2_rn(v0 - __half2float(__low2half(h2)),
                                   v1 - __half2float(__high2half(h2)));
    hw = *reinterpret_cast<uint32_t*>(&h2);
    lw = *reinterpret_cast<uint32_t*>(&l2);
}

// compensated accumulate: (s,c) += x*w with product error captured via FMA
__device__ __forceinline__ void comp_fma(float& s, float& c, float x, float w) {
    float p = x * w;
    float perr = fmaf(x, w, -p);
    float t = s + p;
    float z = t - s;
    float serr = (s - (t - z)) + (p - z);
    s = t;
    c += perr + serr;
}
__device__ __forceinline__ void comp_merge(float& s, float& c, float s2, float c2) {
    float t = s + s2;
    float z = t - s;
    float serr = (s - (t - z)) + (s2 - z);
    s = t;
    c += c2 + serr;
}

// ---------------- counter reset ----------------
__global__ void k_reset() { if (threadIdx.x < NE) g_counts[threadIdx.x] = 0; }

// ---------------- gating (top-2 per token, compensated fp32) ----------------
__global__ void k_gating(const float* __restrict__ x0, const float* __restrict__ Wg) {
    const int warp = threadIdx.x >> 5, lane = threadIdx.x & 31;
    const int t = blockIdx.x * (blockDim.x >> 5) + warp;
    float s[NE], c[NE];
#pragma unroll
    for (int e = 0; e < NE; e++) { s[e] = 0.f; c[e] = 0.f; }
    const float* x = x0 + (size_t)t * DM;
    for (int k = lane; k < DM; k += 32) {
        float xv = x[k];
        const float4 w0 = *reinterpret_cast<const float4*>(Wg + (size_t)k * NE);
        const float4 w1 = *reinterpret_cast<const float4*>(Wg + (size_t)k * NE + 4);
        comp_fma(s[0], c[0], xv, w0.x); comp_fma(s[1], c[1], xv, w0.y);
        comp_fma(s[2], c[2], xv, w0.z); comp_fma(s[3], c[3], xv, w0.w);
        comp_fma(s[4], c[4], xv, w1.x); comp_fma(s[5], c[5], xv, w1.y);
        comp_fma(s[6], c[6], xv, w1.z); comp_fma(s[7], c[7], xv, w1.w);
    }
#pragma unroll
    for (int off = 16; off > 0; off >>= 1)
#pragma unroll
        for (int e = 0; e < NE; e++) {
            float s2 = __shfl_xor_sync(0xffffffffu, s[e], off);
            float c2 = __shfl_xor_sync(0xffffffffu, c[e], off);
            comp_merge(s[e], c[e], s2, c2);
        }
    if (lane == 0) {
        double acc[NE];
#pragma unroll
        for (int e = 0; e < NE; e++) acc[e] = (double)s[e] + (double)c[e];
        int i1 = 0; double v1 = acc[0];
#pragma unroll
        for (int e = 1; e < NE; e++) if (acc[e] > v1) { v1 = acc[e]; i1 = e; }
        int i2 = -1; double v2 = -1.0e300;
#pragma unroll
        for (int e = 0; e < NE; e++) if (e != i1 && acc[e] > v2) { v2 = acc[e]; i2 = e; }
        g_top2[t] = i1 | (i2 << 8);
        atomicAdd(&g_counts[i1], 1);
        atomicAdd(&g_counts[i2], 1);
    }
}

// ---------------- cvt xl -> fp16 hi/lo (vectorized) ----------------
__global__ void k_cvt_x(const float* __restrict__ x) {
    const size_t total4 = (size_t)TOKENS * DM / 4;
    const size_t stride = (size_t)gridDim.x * blockDim.x;
    for (size_t i = (size_t)blockIdx.x * blockDim.x + threadIdx.x; i < total4; i += stride) {
        float4 v = *reinterpret_cast<const float4*>(x + i * 4);
        uint32_t h01, l01, h23, l23;
        split2(v.x, v.y, h01, l01);
        split2(v.z, v.w, h23, l23);
        *reinterpret_cast<uint2*>(g_xl_hi + i * 4) = make_uint2(h01, h23);
        *reinterpret_cast<uint2*>(g_xl_lo + i * 4) = make_uint2(l01, l23);
    }
}

// ---------------- transpose-convert W[e][k][n] -> O[e][n][k] fp16 hi only ----------
// MODE 0: W1 -> g_w1t_hi. MODE 1: W2 -> g_w2t_hi. 64(k) x 32(n) tiles, packed stores.
template <int K, int N, int MODE>
__global__ void k_wt(const float* __restrict__ W) {
    __shared__ float t[64][33];
    const int e = blockIdx.z;
    const int n0 = blockIdx.x * 32, k0 = blockIdx.y * 64;
    const float* Wp = W + (size_t)e * K * N;
    const int tx = threadIdx.x, ty = threadIdx.y;   // 32 x 8
#pragma unroll
    for (int j = 0; j < 8; j++)
        t[ty + j * 8][tx] = Wp[(size_t)(k0 + ty + j * 8) * N + n0 + tx];
    __syncthreads();
#pragma unroll
    for (int j = 0; j < 4; j++) {
        const int nl = ty + j * 8;
        float v0 = t[tx * 2][nl];
        float v1 = t[tx * 2 + 1][nl];
        const size_t o = ((size_t)e * N + n0 + nl) * K + k0 + tx * 2;
        __half2 h2 = __floats2half2_rn(v0, v1);
        uint32_t hw = *reinterpret_cast<uint32_t*>(&h2);
        if (MODE == 0) *reinterpret_cast<uint32_t*>(g_w1t_hi + o) = hw;
        else           *reinterpret_cast<uint32_t*>(g_w2t_hi + o) = hw;
    }
}

// ---------------- scan (tiny) ----------------
__global__ void k_scan() {
    int s = 0;
    for (int e = 0; e < NE; e++) { g_offsets[e] = s; g_cursor[e] = s; s += g_counts[e]; }
}

// ---------------- parallel scatter ----------------
__global__ void k_scatter() {
    const int t = blockIdx.x * blockDim.x + threadIdx.x;
    const int p = g_top2[t];
    const int s1 = atomicAdd(&g_cursor[p & 0xff], 1);
    const int s2 = atomicAdd(&g_cursor[(p >> 8) & 0xff], 1);
    g_tokens[s1] = t;
    g_tokens[s2] = t;
    g_slots[t] = make_int2(s1, s2);
}

// ---------------- HMMA pass: 4 m-tiles x 4 n-tiles ----------------
__device__ __forceinline__ void pass(float acc[4][4][4], const uint32_t af[4][4],
                                     const uint32_t b[2][4]) {
#pragma unroll
    for (int mt = 0; mt < 4; mt++)
#pragma unroll
        for (int nt = 0; nt < 4; nt++)
            mma_fp16(acc[mt][nt], af[mt], &b[nt >> 1][(nt & 1) * 2]);
}

// fp16 2-pass split GEMM: D = (Ahi + Alo) @ Bhi^T  (drops A*Blo, ~2e-4 rel)
template <int KT, int NTOT, bool IS_G1>
__global__ __launch_bounds__(256, 2) void k_hmma(const float* __restrict__ bias) {
    const int e = blockIdx.z;
    const int cnt = g_counts[e];
    const int m0 = blockIdx.y * BM;
    if (m0 >= cnt) return;
    const int off = g_offsets[e];
    const int n0 = blockIdx.x * BN;
    const int tid = threadIdx.x;

    extern __shared__ char smem[];
    __shared__ int s_rows[BM];
    const uint32_t sb = smem_u32(smem);

    if (tid < BM) {
        int mm = m0 + tid;
        int mc = mm < cnt ? mm : cnt - 1;
        s_rows[tid] = IS_G1 ? g_tokens[off + mc] : (off + mc);
    }
    __syncthreads();

    const __half* Ahi = IS_G1 ? g_xl_hi : g_h_hi;
    const __half* Alo = IS_G1 ? g_xl_lo : g_h_lo;
    const __half* Bhi = (IS_G1 ? g_w1t_hi : g_w2t_hi) + ((size_t)e * NTOT + n0) * KT;

    const int rF = tid >> 2, cF = tid & 3;
    const uint32_t d0 = swz(rF, cF);
    const uint32_t d1 = d0 + 64 * 64;
    const __half* ah0 = Ahi + (size_t)s_rows[rF] * KT + cF * 8;
    const __half* al0 = Alo + (size_t)s_rows[rF] * KT + cF * 8;
    const __half* ah1 = Ahi + (size_t)s_rows[rF + 64] * KT + cF * 8;
    const __half* al1 = Alo + (size_t)s_rows[rF + 64] * KT + cF * 8;
    const __half* bh0 = Bhi + (size_t)rF * KT + cF * 8;
    const __half* bh1 = Bhi + (size_t)(rF + 64) * KT + cF * 8;

#define FILL(sidx, k0_) do {                                        \
        uint32_t _s = sb + (sidx) * STB;                            \
        cp_async16(_s + d0, ah0 + (k0_));                           \
        cp_async16(_s + d1, ah1 + (k0_));                           \
        cp_async16(_s + O_AL + d0, al0 + (k0_));                    \
        cp_async16(_s + O_AL + d1, al1 + (k0_));                    \
        cp_async16(_s + O_BH + d0, bh0 + (k0_));                    \
        cp_async16(_s + O_BH + d1, bh1 + (k0_));                    \
    } while (0)

    const int lane = tid & 31, wid = tid >> 5;
    const int warp_m = wid >> 2, warp_n = wid & 3;
    const int rowA = warp_m * 64 + (lane & 15);
    const int rowB = warp_n * 32 + ((lane >> 4) << 3) + (lane & 7);
    const uint32_t aoff = swz(rowA, lane >> 4);
    const uint32_t boff = swz(rowB, (lane >> 3) & 1);

    float acc[4][4][4];
#pragma unroll
    for (int i = 0; i < 4; i++)
#pragma unroll
        for (int j = 0; j < 4; j++)
#pragma unroll
            for (int q = 0; q < 4; q++) acc[i][j][q] = 0.f;

    constexpr int NKC = KT / BK;
    FILL(0, 0);  cp_commit();
    FILL(1, BK); cp_commit();

    for (int kc = 0; kc < NKC; kc++) {
        cp_wait<1>();
        __syncthreads();
        if (kc + 2 < NKC) { FILL((kc + 2) % NSTG, (kc + 2) * BK); }
        cp_commit();
        const uint32_t st = sb + (kc % NSTG) * STB;
#pragma unroll
        for (int k16 = 0; k16 < 2; k16++) {
            const uint32_t ab = st + (aoff ^ (k16 << 5));
            const uint32_t bb = st + O_BH + (boff ^ (k16 << 5));
            uint32_t af[4][4], bh[2][4];
#pragma unroll
            for (int mt = 0; mt < 4; mt++) ldsm4(af[mt], ab + mt * 1024);
#pragma unroll
            for (int p = 0; p < 2; p++)   ldsm4(bh[p], bb + p * 1024);
            pass(acc, af, bh);                              // Ahi * Bhi
#pragma unroll
            for (int mt = 0; mt < 4; mt++) ldsm4(af[mt], ab + O_AL + mt * 1024);
            pass(acc, af, bh);                              // Alo * Bhi
        }
    }
#undef FILL

    // ---- epilogue ----
    const int g = lane >> 2, c2 = (lane & 3) * 2;
    const float* bp = bias + (size_t)e * NTOT;
#pragma unroll
    for (int mt = 0; mt < 4; mt++) {
#pragma unroll
        for (int nt = 0; nt < 4; nt++) {
            const int n = n0 + warp_n * 32 + nt * 8 + c2;
            const float bv0 = __ldg(bp + n), bv1 = __ldg(bp + n + 1);
#pragma unroll
            for (int h = 0; h < 2; h++) {
                const int m = m0 + warp_m * 64 + mt * 16 + g + h * 8;
                if (m >= cnt) continue;
                float v0 = acc[mt][nt][h * 2 + 0] + bv0;
                float v1 = acc[mt][nt][h * 2 + 1] + bv1;
                if (IS_G1) {
                    v0 = fmaxf(v0, 0.f); v1 = fmaxf(v1, 0.f);
                    uint32_t hw, lw;
                    split2(v0, v1, hw, lw);
                    const size_t o = (size_t)(off + m) * DH + n;
                    *reinterpret_cast<uint32_t*>(g_h_hi + o) = hw;
                    *reinterpret_cast<uint32_t*>(g_h_lo + o) = lw;
                } else {
                    float2 v = make_float2(v0, v1);
                    *reinterpret_cast<float2*>(g_o + (size_t)(off + m) * DM + n) = v;
                }
            }
        }
    }
}

// ---------------- combine out[t] = g_o[s1] + g_o[s2] ----------------
__global__ void k_combine(float* __restrict__ out) {
    const int i = blockIdx.x * blockDim.x + threadIdx.x;   // float4 index
    const int t = i >> 8, cc = i & 255;
    const int2 s = g_slots[t];
    const float4 a = *reinterpret_cast<const float4*>(g_o + (size_t)s.x * DM + cc * 4);
    const float4 b = *reinterpret_cast<const float4*>(g_o + (size_t)s.y * DM + cc * 4);
    float4 r = make_float4(a.x + b.x, a.y + b.y, a.z + b.z, a.w + b.w);
    *reinterpret_cast<float4*>(out + (size_t)t * DM + cc * 4) = r;
}

// ---------------- launch ----------------
extern "C" void kernel_launch(void* const* d_in, const int* in_sizes, int n_in,
                              void* d_out, int out_size) {
    const float* xl = (const float*)d_in[0];
    const float* x0 = (const float*)d_in[1];
    const float* Wg = (const float*)d_in[2];
    const float* W1 = (const float*)d_in[3];
    const float* b1 = (const float*)d_in[4];
    const float* W2 = (const float*)d_in[5];
    const float* b2 = (const float*)d_in[6];
    float* out = (float*)d_out;

    cudaFuncSetAttribute((const void*)k_hmma<DM, DH, true>,
                         cudaFuncAttributeMaxDynamicSharedMemorySize, SMEM_TOTAL);
    cudaFuncSetAttribute((const void*)k_hmma<DH, DM, false>,
                         cudaFuncAttributeMaxDynamicSharedMemorySize, SMEM_TOTAL);

    k_reset<<<1, 32>>>();
    k_gating<<<TOKENS / 8, 256>>>(x0, Wg);
    k_cvt_x<<<512, 256>>>(xl);
    k_wt<DM, DH, 0><<<dim3(DH / 32, DM / 64, NE), dim3(32, 8)>>>(W1);
    k_wt<DH, DM, 1><<<dim3(DM / 32, DH / 64, NE), dim3(32, 8)>>>(W2);
    k_scan<<<1, 1>>>();
    k_scatter<<<TOKENS / 256, 256>>>();
    // GEMM1: fp16 2-pass, relu -> h (fp16 hi/lo)
    k_hmma<DM, DH, true><<<dim3(DH / BN, TOKENS / BM, NE), 256, SMEM_TOTAL>>>(b1);
    // GEMM2: fp16 2-pass -> g_o
    k_hmma<DH, DM, false><<<dim3(DM / BN, TOKENS / BM, NE), 256, SMEM_TOTAL>>>(b2);
    k_combine<<<(TOKENS * DM / 4) / 256, 256>>>(out);
}

// round 15
// speedup vs baseline: 2.7356x; 1.6996x over previous
#include <cuda_runtime.h>
#include <cuda_fp16.h>
#include <cstdint>

#define TOKENS 8192
#define DM 1024
#define DH 4096
#define NE 8
#define NSLOTS (TOKENS * 2)

// GEMM tiling: CTA 128x128x32, 8 warps (2m x 4n), warp tile 64x32, plain fp16 1-pass.
// SMEM: XOR-swizzled 64B rows. Stage = A(8KB) + B(8KB) = 16KB; 4 stages; 2 CTA/SM.
#define BM 128
#define BN 128
#define BK 32
#define NSTG 4
#define O_B 8192
#define STB 16384
#define SMEM_TOTAL (NSTG * STB)   // 65536

// ---------------- scratch globals (fp16) ----------------
__device__ __half g_xl[(size_t)TOKENS * DM];
__device__ __half g_w1t[(size_t)NE * DH * DM];   // [E][N=DH][K=DM]
__device__ __half g_w2t[(size_t)NE * DM * DH];   // [E][N=DM][K=DH]
__device__ __half g_h[(size_t)NSLOTS * DH];
__device__ float g_o[(size_t)NSLOTS * DM];
__device__ int g_top2[TOKENS];
__device__ int2 g_slots[TOKENS];
__device__ int g_counts[NE];
__device__ int g_offsets[NE];
__device__ int g_cursor[NE];
__device__ int g_tokens[NSLOTS];

// ---------------- PTX helpers ----------------
__device__ __forceinline__ uint32_t smem_u32(const void* p) {
    uint32_t a;
    asm("{ .reg .u64 t; cvta.to.shared.u64 t, %1; cvt.u32.u64 %0, t; }" : "=r"(a) : "l"(p));
    return a;
}
__device__ __forceinline__ void cp_async16(uint32_t dst, const void* src) {
    asm volatile("cp.async.cg.shared.global [%0], [%1], 16;" :: "r"(dst), "l"(src));
}
__device__ __forceinline__ void cp_commit() { asm volatile("cp.async.commit_group;" ::: "memory"); }
template <int N>
__device__ __forceinline__ void cp_wait() { asm volatile("cp.async.wait_group %0;" :: "n"(N) : "memory"); }

__device__ __forceinline__ void ldsm4(uint32_t* r, uint32_t addr) {
    asm volatile("ldmatrix.sync.aligned.m8n8.x4.shared.b16 {%0,%1,%2,%3}, [%4];"
                 : "=r"(r[0]), "=r"(r[1]), "=r"(r[2]), "=r"(r[3]) : "r"(addr));
}
__device__ __forceinline__ void mma_fp16(float* c, const uint32_t* a, const uint32_t* b) {
    asm volatile(
        "mma.sync.aligned.m16n8k16.row.col.f32.f16.f16.f32 "
        "{%0,%1,%2,%3}, {%4,%5,%6,%7}, {%8,%9}, {%0,%1,%2,%3};"
        : "+f"(c[0]), "+f"(c[1]), "+f"(c[2]), "+f"(c[3])
        : "r"(a[0]), "r"(a[1]), "r"(a[2]), "r"(a[3]), "r"(b[0]), "r"(b[1]));
}

// swizzled offset within a 128x64B tile: row r (0..127), 16B chunk c (0..3)
__device__ __forceinline__ uint32_t swz(int r, int c) {
    return (uint32_t)r * 64u + (uint32_t)((c ^ ((r >> 1) & 3)) << 4);
}

// compensated accumulate: (s,c) += x*w with product error captured via FMA
__device__ __forceinline__ void comp_fma(float& s, float& c, float x, float w) {
    float p = x * w;
    float perr = fmaf(x, w, -p);
    float t = s + p;
    float z = t - s;
    float serr = (s - (t - z)) + (p - z);
    s = t;
    c += perr + serr;
}
__device__ __forceinline__ void comp_merge(float& s, float& c, float s2, float c2) {
    float t = s + s2;
    float z = t - s;
    float serr = (s - (t - z)) + (s2 - z);
    s = t;
    c += c2 + serr;
}

// ---------------- counter reset ----------------
__global__ void k_reset() { if (threadIdx.x < NE) g_counts[threadIdx.x] = 0; }

// ---------------- gating (top-2 per token, compensated fp32) ----------------
__global__ void k_gating(const float* __restrict__ x0, const float* __restrict__ Wg) {
    const int warp = threadIdx.x >> 5, lane = threadIdx.x & 31;
    const int t = blockIdx.x * (blockDim.x >> 5) + warp;
    float s[NE], c[NE];
#pragma unroll
    for (int e = 0; e < NE; e++) { s[e] = 0.f; c[e] = 0.f; }
    const float* x = x0 + (size_t)t * DM;
    for (int k = lane; k < DM; k += 32) {
        float xv = x[k];
        const float4 w0 = *reinterpret_cast<const float4*>(Wg + (size_t)k * NE);
        const float4 w1 = *reinterpret_cast<const float4*>(Wg + (size_t)k * NE + 4);
        comp_fma(s[0], c[0], xv, w0.x); comp_fma(s[1], c[1], xv, w0.y);
        comp_fma(s[2], c[2], xv, w0.z); comp_fma(s[3], c[3], xv, w0.w);
        comp_fma(s[4], c[4], xv, w1.x); comp_fma(s[5], c[5], xv, w1.y);
        comp_fma(s[6], c[6], xv, w1.z); comp_fma(s[7], c[7], xv, w1.w);
    }
#pragma unroll
    for (int off = 16; off > 0; off >>= 1)
#pragma unroll
        for (int e = 0; e < NE; e++) {
            float s2 = __shfl_xor_sync(0xffffffffu, s[e], off);
            float c2 = __shfl_xor_sync(0xffffffffu, c[e], off);
            comp_merge(s[e], c[e], s2, c2);
        }
    if (lane == 0) {
        double acc[NE];
#pragma unroll
        for (int e = 0; e < NE; e++) acc[e] = (double)s[e] + (double)c[e];
        int i1 = 0; double v1 = acc[0];
#pragma unroll
        for (int e = 1; e < NE; e++) if (acc[e] > v1) { v1 = acc[e]; i1 = e; }
        int i2 = -1; double v2 = -1.0e300;
#pragma unroll
        for (int e = 0; e < NE; e++) if (e != i1 && acc[e] > v2) { v2 = acc[e]; i2 = e; }
        g_top2[t] = i1 | (i2 << 8);
        atomicAdd(&g_counts[i1], 1);
        atomicAdd(&g_counts[i2], 1);
    }
}

// ---------------- cvt xl -> fp16 (vectorized) ----------------
__global__ void k_cvt_x(const float* __restrict__ x) {
    const size_t total4 = (size_t)TOKENS * DM / 4;
    const size_t stride = (size_t)gridDim.x * blockDim.x;
    for (size_t i = (size_t)blockIdx.x * blockDim.x + threadIdx.x; i < total4; i += stride) {
        float4 v = *reinterpret_cast<const float4*>(x + i * 4);
        __half2 h01 = __floats2half2_rn(v.x, v.y);
        __half2 h23 = __floats2half2_rn(v.z, v.w);
        *reinterpret_cast<uint2*>(g_xl + i * 4) =
            make_uint2(*(uint32_t*)&h01, *(uint32_t*)&h23);
    }
}

// ---------------- transpose-convert W[e][k][n] -> O[e][n][k] fp16 ----------
// MODE 0: W1 -> g_w1t. MODE 1: W2 -> g_w2t. 64(k) x 32(n) tiles, packed stores.
template <int K, int N, int MODE>
__global__ void k_wt(const float* __restrict__ W) {
    __shared__ float t[64][33];
    const int e = blockIdx.z;
    const int n0 = blockIdx.x * 32, k0 = blockIdx.y * 64;
    const float* Wp = W + (size_t)e * K * N;
    const int tx = threadIdx.x, ty = threadIdx.y;   // 32 x 8
#pragma unroll
    for (int j = 0; j < 8; j++)
        t[ty + j * 8][tx] = Wp[(size_t)(k0 + ty + j * 8) * N + n0 + tx];
    __syncthreads();
#pragma unroll
    for (int j = 0; j < 4; j++) {
        const int nl = ty + j * 8;
        __half2 h2 = __floats2half2_rn(t[tx * 2][nl], t[tx * 2 + 1][nl]);
        const size_t o = ((size_t)e * N + n0 + nl) * K + k0 + tx * 2;
        if (MODE == 0) *reinterpret_cast<uint32_t*>(g_w1t + o) = *(uint32_t*)&h2;
        else           *reinterpret_cast<uint32_t*>(g_w2t + o) = *(uint32_t*)&h2;
    }
}

// ---------------- scan (tiny) ----------------
__global__ void k_scan() {
    int s = 0;
    for (int e = 0; e < NE; e++) { g_offsets[e] = s; g_cursor[e] = s; s += g_counts[e]; }
}

// ---------------- parallel scatter ----------------
__global__ void k_scatter() {
    const int t = blockIdx.x * blockDim.x + threadIdx.x;
    const int p = g_top2[t];
    const int s1 = atomicAdd(&g_cursor[p & 0xff], 1);
    const int s2 = atomicAdd(&g_cursor[(p >> 8) & 0xff], 1);
    g_tokens[s1] = t;
    g_tokens[s2] = t;
    g_slots[t] = make_int2(s1, s2);
}

// ---------------- plain fp16 grouped GEMM, fp32 accumulate ----------------
template <int KT, int NTOT, bool IS_G1>
__global__ __launch_bounds__(256, 2) void k_hmma(const float* __restrict__ bias) {
    const int e = blockIdx.z;
    const int cnt = g_counts[e];
    const int m0 = blockIdx.y * BM;
    if (m0 >= cnt) return;
    const int off = g_offsets[e];
    const int n0 = blockIdx.x * BN;
    const int tid = threadIdx.x;

    extern __shared__ char smem[];
    __shared__ int s_rows[BM];
    const uint32_t sb = smem_u32(smem);

    if (tid < BM) {
        int mm = m0 + tid;
        int mc = mm < cnt ? mm : cnt - 1;
        s_rows[tid] = IS_G1 ? g_tokens[off + mc] : (off + mc);
    }
    __syncthreads();

    const __half* A = IS_G1 ? g_xl : g_h;
    const __half* B = (IS_G1 ? g_w1t : g_w2t) + ((size_t)e * NTOT + n0) * KT;

    const int rF = tid >> 2, cF = tid & 3;
    const uint32_t d0 = swz(rF, cF);
    const uint32_t d1 = d0 + 64 * 64;
    const __half* a0 = A + (size_t)s_rows[rF] * KT + cF * 8;
    const __half* a1 = A + (size_t)s_rows[rF + 64] * KT + cF * 8;
    const __half* b0 = B + (size_t)rF * KT + cF * 8;
    const __half* b1 = B + (size_t)(rF + 64) * KT + cF * 8;

#define FILL(sidx, k0_) do {                                        \
        uint32_t _s = sb + (sidx) * STB;                            \
        cp_async16(_s + d0, a0 + (k0_));                            \
        cp_async16(_s + d1, a1 + (k0_));                            \
        cp_async16(_s + O_B + d0, b0 + (k0_));                      \
        cp_async16(_s + O_B + d1, b1 + (k0_));                      \
    } while (0)

    const int lane = tid & 31, wid = tid >> 5;
    const int warp_m = wid >> 2, warp_n = wid & 3;
    const int rowA = warp_m * 64 + (lane & 15);
    const int rowB = warp_n * 32 + ((lane >> 4) << 3) + (lane & 7);
    const uint32_t aoff = swz(rowA, lane >> 4);
    const uint32_t boff = swz(rowB, (lane >> 3) & 1);

    float acc[4][4][4];
#pragma unroll
    for (int i = 0; i < 4; i++)
#pragma unroll
        for (int j = 0; j < 4; j++)
#pragma unroll
            for (int q = 0; q < 4; q++) acc[i][j][q] = 0.f;

    constexpr int NKC = KT / BK;
    FILL(0, 0);       cp_commit();
    FILL(1, BK);      cp_commit();
    FILL(2, 2 * BK);  cp_commit();

    for (int kc = 0; kc < NKC; kc++) {
        cp_wait<2>();
        __syncthreads();
        if (kc + 3 < NKC) { FILL((kc + 3) % NSTG, (kc + 3) * BK); }
        cp_commit();
        const uint32_t st = sb + (kc % NSTG) * STB;
#pragma unroll
        for (int k16 = 0; k16 < 2; k16++) {
            const uint32_t ab = st + (aoff ^ (k16 << 5));
            const uint32_t bb = st + O_B + (boff ^ (k16 << 5));
            uint32_t af[4][4], bf[2][4];
#pragma unroll
            for (int mt = 0; mt < 4; mt++) ldsm4(af[mt], ab + mt * 1024);
#pragma unroll
            for (int p = 0; p < 2; p++)   ldsm4(bf[p], bb + p * 1024);
#pragma unroll
            for (int mt = 0; mt < 4; mt++)
#pragma unroll
                for (int nt = 0; nt < 4; nt++)
                    mma_fp16(acc[mt][nt], af[mt], &bf[nt >> 1][(nt & 1) * 2]);
        }
    }
#undef FILL

    // ---- epilogue ----
    const int g = lane >> 2, c2 = (lane & 3) * 2;
    const float* bp = bias + (size_t)e * NTOT;
#pragma unroll
    for (int mt = 0; mt < 4; mt++) {
#pragma unroll
        for (int nt = 0; nt < 4; nt++) {
            const int n = n0 + warp_n * 32 + nt * 8 + c2;
            const float bv0 = __ldg(bp + n), bv1 = __ldg(bp + n + 1);
#pragma unroll
            for (int h = 0; h < 2; h++) {
                const int m = m0 + warp_m * 64 + mt * 16 + g + h * 8;
                if (m >= cnt) continue;
                float v0 = acc[mt][nt][h * 2 + 0] + bv0;
                float v1 = acc[mt][nt][h * 2 + 1] + bv1;
                if (IS_G1) {
                    __half2 h2 = __floats2half2_rn(fmaxf(v0, 0.f), fmaxf(v1, 0.f));
                    *reinterpret_cast<uint32_t*>(g_h + (size_t)(off + m) * DH + n) =
                        *(uint32_t*)&h2;
                } else {
                    float2 v = make_float2(v0, v1);
                    *reinterpret_cast<float2*>(g_o + (size_t)(off + m) * DM + n) = v;
                }
            }
        }
    }
}

// ---------------- combine out[t] = g_o[s1] + g_o[s2] ----------------
__global__ void k_combine(float* __restrict__ out) {
    const int i = blockIdx.x * blockDim.x + threadIdx.x;   // float4 index
    const int t = i >> 8, cc = i & 255;
    const int2 s = g_slots[t];
    const float4 a = *reinterpret_cast<const float4*>(g_o + (size_t)s.x * DM + cc * 4);
    const float4 b = *reinterpret_cast<const float4*>(g_o + (size_t)s.y * DM + cc * 4);
    float4 r = make_float4(a.x + b.x, a.y + b.y, a.z + b.z, a.w + b.w);
    *reinterpret_cast<float4*>(out + (size_t)t * DM + cc * 4) = r;
}

// ---------------- launch ----------------
extern "C" void kernel_launch(void* const* d_in, const int* in_sizes, int n_in,
                              void* d_out, int out_size) {
    const float* xl = (const float*)d_in[0];
    const float* x0 = (const float*)d_in[1];
    const float* Wg = (const float*)d_in[2];
    const float* W1 = (const float*)d_in[3];
    const float* b1 = (const float*)d_in[4];
    const float* W2 = (const float*)d_in[5];
    const float* b2 = (const float*)d_in[6];
    float* out = (float*)d_out;

    cudaFuncSetAttribute((const void*)k_hmma<DM, DH, true>,
                         cudaFuncAttributeMaxDynamicSharedMemorySize, SMEM_TOTAL);
    cudaFuncSetAttribute((const void*)k_hmma<DH, DM, false>,
                         cudaFuncAttributeMaxDynamicSharedMemorySize, SMEM_TOTAL);

    k_reset<<<1, 32>>>();
    k_gating<<<TOKENS / 8, 256>>>(x0, Wg);
    k_cvt_x<<<512, 256>>>(xl);
    k_wt<DM, DH, 0><<<dim3(DH / 32, DM / 64, NE), dim3(32, 8)>>>(W1);
    k_wt<DH, DM, 1><<<dim3(DM / 32, DH / 64, NE), dim3(32, 8)>>>(W2);
    k_scan<<<1, 1>>>();
    k_scatter<<<TOKENS / 256, 256>>>();
    // GEMM1: fp16 1-pass, relu -> h (fp16)
    k_hmma<DM, DH, true><<<dim3(DH / BN, TOKENS / BM, NE), 256, SMEM_TOTAL>>>(b1);
    // GEMM2: fp16 1-pass -> g_o
    k_hmma<DH, DM, false><<<dim3(DM / BN, TOKENS / BM, NE), 256, SMEM_TOTAL>>>(b2);
    k_combine<<<(TOKENS * DM / 4) / 256, 256>>>(out);
}